// round 12
// baseline (speedup 1.0000x reference)
#include <cuda_runtime.h>
#include <cuda_bf16.h>
#include <math.h>

typedef unsigned u32;
typedef unsigned long long u64;

#define BATCH 2
#define SEQN 2048
#define EMB 1024
#define NH 16
#define HD 64
#define NB 32
#define MROWS (BATCH*SEQN)   // 4096

// ---------------- scratch: static device globals ----------------
__device__ __nv_bfloat16 g_hs_h[MROWS*EMB], g_hs_l[MROWS*EMB];
__device__ __nv_bfloat16 g_wq_h[EMB*EMB], g_wq_l[EMB*EMB];
__device__ __nv_bfloat16 g_wk_h[EMB*EMB], g_wk_l[EMB*EMB];
__device__ __nv_bfloat16 g_wv_h[EMB*EMB], g_wv_l[EMB*EMB];
__device__ __nv_bfloat16 g_wo_h[EMB*EMB], g_wo_l[EMB*EMB];
__device__ __nv_bfloat16 g_q_h[MROWS*EMB], g_q_l[MROWS*EMB];
__device__ __nv_bfloat16 g_k_h[MROWS*EMB], g_k_l[MROWS*EMB];
__device__ __nv_bfloat16 g_v_h[MROWS*EMB], g_v_l[MROWS*EMB];
__device__ __nv_bfloat16 g_c_h[MROWS*EMB], g_c_l[MROWS*EMB];
__device__ unsigned g_blockmask[NB];

// ---------------- asm helpers ----------------
__device__ __forceinline__ u32 smem_u32(const void* p) {
    return (u32)__cvta_generic_to_shared(p);
}
__device__ __forceinline__ void ldsm4(u32 a[4], u32 addr) {
    asm volatile("ldmatrix.sync.aligned.m8n8.x4.shared.b16 {%0,%1,%2,%3}, [%4];"
        : "=r"(a[0]), "=r"(a[1]), "=r"(a[2]), "=r"(a[3]) : "r"(addr));
}
__device__ __forceinline__ void ldsm4t(u32 a[4], u32 addr) {
    asm volatile("ldmatrix.sync.aligned.m8n8.x4.trans.shared.b16 {%0,%1,%2,%3}, [%4];"
        : "=r"(a[0]), "=r"(a[1]), "=r"(a[2]), "=r"(a[3]) : "r"(addr));
}
__device__ __forceinline__ void mma16816(float d[4], const u32 a[4], u32 b0, u32 b1) {
    asm volatile("mma.sync.aligned.m16n8k16.row.col.f32.bf16.bf16.f32 "
        "{%0,%1,%2,%3},{%4,%5,%6,%7},{%8,%9},{%0,%1,%2,%3};"
        : "+f"(d[0]), "+f"(d[1]), "+f"(d[2]), "+f"(d[3])
        : "r"(a[0]), "r"(a[1]), "r"(a[2]), "r"(a[3]), "r"(b0), "r"(b1));
}
__device__ __forceinline__ void cpa16(u32 dst, const void* src) {
    asm volatile("cp.async.cg.shared.global [%0], [%1], 16;" :: "r"(dst), "l"(src));
}
#define CP_COMMIT asm volatile("cp.async.commit_group;" ::: "memory")
#define CP_WAIT0  asm volatile("cp.async.wait_group 0;" ::: "memory")
#define CP_WAIT1  asm volatile("cp.async.wait_group 1;" ::: "memory")

// swizzles: 64B-row tiles (GEMM) and 128B-row tiles (attention)
__device__ __forceinline__ u32 swzG(u32 off) { return off ^ (((off >> 7) & 3u) << 4); }
__device__ __forceinline__ u32 swzA(u32 off) { return off ^ ((off >> 3) & 0x70u); }

// split two fp32 into packed bf16 hi-pair and lo-pair
__device__ __forceinline__ void split_pair(float x0, float x1, u32& h, u32& l) {
    __nv_bfloat16 h0 = __float2bfloat16(x0), h1 = __float2bfloat16(x1);
    float r0 = x0 - __bfloat162float(h0), r1 = x1 - __bfloat162float(h1);
    __nv_bfloat16 l0 = __float2bfloat16(r0), l1 = __float2bfloat16(r1);
    __nv_bfloat162 hp; hp.x = h0; hp.y = h1;
    __nv_bfloat162 lp; lp.x = l0; lp.y = l1;
    h = *reinterpret_cast<u32*>(&hp);
    l = *reinterpret_cast<u32*>(&lp);
}

// ---------------- MT19937 mask init, warp-parallel twist ----------------
#define NGEN_BLOCKS 4
__global__ void init_mask_kernel() {
    __shared__ unsigned mt[624];
    __shared__ unsigned rnd[NGEN_BLOCKS * 624];
    const int t = threadIdx.x;

    if (t == 0) {
        unsigned s = 0u;
        for (int i = 0; i < 624; ++i) { mt[i] = s; s = 1812433253u * (s ^ (s >> 30)) + (unsigned)i + 1u; }
    }
    __syncwarp();

    auto twist_range = [&](int lo, int hi) {
        for (int base = lo; base < hi; base += 32) {
            int i = base + t;
            unsigned nv = 0; bool act = (i < hi);
            if (act) {
                unsigned y = (mt[i] & 0x80000000u) | (mt[(i + 1) % 624] & 0x7fffffffu);
                nv = mt[(i + 397) % 624] ^ (y >> 1) ^ ((y & 1u) ? 0x9908b0dfu : 0u);
            }
            __syncwarp();
            if (act) mt[i] = nv;
            __syncwarp();
        }
    };

    for (int blk = 0; blk < NGEN_BLOCKS; ++blk) {
        twist_range(0, 227);
        twist_range(227, 454);
        twist_range(454, 624);
        for (int i = t; i < 624; i += 32) {
            unsigned y = mt[i];
            y ^= y >> 11; y ^= (y << 7) & 0x9d2c5680u; y ^= (y << 15) & 0xefc60000u; y ^= y >> 18;
            rnd[blk * 624 + i] = y;
        }
        __syncwarp();
    }

    if (t != 0) return;

    int idx = 0;
    auto next32 = [&]() -> unsigned { return rnd[idx++]; };
    auto rand_interval = [&](unsigned maxv) -> unsigned {
        if (maxv == 0u) return 0u;
        unsigned mask = maxv;
        mask |= mask >> 1; mask |= mask >> 2; mask |= mask >> 4; mask |= mask >> 8; mask |= mask >> 16;
        unsigned v;
        do { v = next32() & mask; } while (v > maxv);
        return v;
    };
    unsigned bm[NB];
    bm[0] = 0xffffffffu;
    for (int qb = 1; qb < NB; ++qb) {
        unsigned m = 1u;
        int lo = qb - 3; if (lo < 0) lo = 0;
        int hi = qb + 3; if (hi > NB - 1) hi = NB - 1;
        for (int kb = lo; kb <= hi; ++kb) m |= (1u << kb);
        bm[qb] = m;
    }
    for (int b = 1; b < NB; ++b) {
        int avail[NB]; int pop = 0;
        for (int x = 1; x < NB; ++x)
            if ((x - b > 3) || (b - x > 3)) avail[pop++] = x;
        if (pop == 0) continue;
        int perm[NB];
        for (int i = 0; i < pop; ++i) perm[i] = i;
        for (int i = pop - 1; i > 0; --i) {
            unsigned j = rand_interval((unsigned)i);
            int tmp = perm[i]; perm[i] = perm[j]; perm[j] = tmp;
        }
        int take = pop < 3 ? pop : 3;
        for (int tsel = 0; tsel < take; ++tsel) bm[b] |= (1u << avail[perm[tsel]]);
    }
    for (int i = 0; i < NB; ++i) g_blockmask[i] = bm[i];
}

__global__ void noop_kernel() {}

// ---------------- fp32 -> bf16 hi/lo splits ----------------
__global__ void split_f32(const float4* __restrict__ src,
                          __nv_bfloat16* __restrict__ h, __nv_bfloat16* __restrict__ l, int n4)
{
    int i = blockIdx.x * blockDim.x + threadIdx.x;
    if (i >= n4) return;
    float4 v = src[i];
    u32 h0, l0, h1, l1;
    split_pair(v.x, v.y, h0, l0);
    split_pair(v.z, v.w, h1, l1);
    u32* hp = (u32*)h + 2 * i;
    u32* lp = (u32*)l + 2 * i;
    hp[0] = h0; hp[1] = h1;
    lp[0] = l0; lp[1] = l1;
}

__global__ void split_w4(const float4* w0, const float4* w1, const float4* w2, const float4* w3,
                         __nv_bfloat16* h0, __nv_bfloat16* l0, __nv_bfloat16* h1, __nv_bfloat16* l1,
                         __nv_bfloat16* h2, __nv_bfloat16* l2, __nv_bfloat16* h3, __nv_bfloat16* l3,
                         int n4)
{
    int i = blockIdx.x * blockDim.x + threadIdx.x;
    if (i >= n4) return;
    int sel = blockIdx.y;
    const float4* src = (sel == 0) ? w0 : (sel == 1) ? w1 : (sel == 2) ? w2 : w3;
    __nv_bfloat16* h = (sel == 0) ? h0 : (sel == 1) ? h1 : (sel == 2) ? h2 : h3;
    __nv_bfloat16* l = (sel == 0) ? l0 : (sel == 1) ? l1 : (sel == 2) ? l2 : l3;
    float4 v = src[i];
    u32 a0, b0, a1, b1;
    split_pair(v.x, v.y, a0, b0);
    split_pair(v.z, v.w, a1, b1);
    u32* hp = (u32*)h + 2 * i;
    u32* lp = (u32*)l + 2 * i;
    hp[0] = a0; hp[1] = a1;
    lp[0] = b0; lp[1] = b1;
}

// ---------------- bf16-split GEMM, 3-stage ring, 1 sync/iter, 2 CTAs/SM ----------------
// CTA 128x128, BK=32, 256 threads (8 warps, 2x4), warp tile 64x32, acc fp32.
__global__ __launch_bounds__(256, 2) void gemm_qkv(
    const __nv_bfloat16* __restrict__ Ah, const __nv_bfloat16* __restrict__ Al,
    const __nv_bfloat16* __restrict__ W0h, const __nv_bfloat16* __restrict__ W0l, const float* __restrict__ b0v,
    const __nv_bfloat16* __restrict__ W1h, const __nv_bfloat16* __restrict__ W1l, const float* __restrict__ b1v,
    const __nv_bfloat16* __restrict__ W2h, const __nv_bfloat16* __restrict__ W2l, const float* __restrict__ b2v,
    __nv_bfloat16* __restrict__ C0h, __nv_bfloat16* __restrict__ C0l,
    __nv_bfloat16* __restrict__ C1h, __nv_bfloat16* __restrict__ C1l,
    __nv_bfloat16* __restrict__ C2h, __nv_bfloat16* __restrict__ C2l,
    float* __restrict__ Cf, int splitOut)
{
    extern __shared__ char smraw[];
    const u32 sbase = smem_u32(smraw);
    const int t = threadIdx.x;
    const int lane = t & 31, warp = t >> 5;
    const int wy = warp >> 2, wx = warp & 3;
    const int m0 = blockIdx.y * 128, n0 = blockIdx.x * 128;
    const int z = blockIdx.z;
    const int K = EMB, N = EMB;

    const __nv_bfloat16* Wh = (z == 0) ? W0h : (z == 1) ? W1h : W2h;
    const __nv_bfloat16* Wl = (z == 0) ? W0l : (z == 1) ? W1l : W2l;
    const float* bias       = (z == 0) ? b0v : (z == 1) ? b1v : b2v;
    __nv_bfloat16* Ch       = (z == 0) ? C0h : (z == 1) ? C1h : C2h;
    __nv_bfloat16* Cl       = (z == 0) ? C0l : (z == 1) ? C1l : C2l;

    const int cch = t & 3;
    const int r0 = t >> 2;
    const u32 d0 = swzG((u32)(r0 * 64 + cch * 16));
    const u32 d1 = swzG((u32)((r0 + 64) * 64 + cch * 16));
    const char* pAh0 = (const char*)(Ah + (size_t)(m0 + r0) * K) + cch * 16;
    const char* pAh1 = (const char*)(Ah + (size_t)(m0 + r0 + 64) * K) + cch * 16;
    const char* pAl0 = (const char*)(Al + (size_t)(m0 + r0) * K) + cch * 16;
    const char* pAl1 = (const char*)(Al + (size_t)(m0 + r0 + 64) * K) + cch * 16;
    const char* pWh0 = (const char*)(Wh + (size_t)(n0 + r0) * K) + cch * 16;
    const char* pWh1 = (const char*)(Wh + (size_t)(n0 + r0 + 64) * K) + cch * 16;
    const char* pWl0 = (const char*)(Wl + (size_t)(n0 + r0) * K) + cch * 16;
    const char* pWl1 = (const char*)(Wl + (size_t)(n0 + r0 + 64) * K) + cch * 16;

    const int lr = lane & 15, lc = lane >> 4;
    u32 offA[4][2], offB[2][2];
#pragma unroll
    for (int i = 0; i < 4; ++i)
#pragma unroll
        for (int s = 0; s < 2; ++s)
            offA[i][s] = swzG((u32)((64 * wy + 16 * i + lr) * 64 + (2 * s + lc) * 16));
#pragma unroll
    for (int jg = 0; jg < 2; ++jg)
#pragma unroll
        for (int s = 0; s < 2; ++s)
            offB[jg][s] = swzG((u32)((32 * wx + 16 * jg + lr) * 64 + (2 * s + lc) * 16));

    float acc[4][4][4];
#pragma unroll
    for (int i = 0; i < 4; ++i)
#pragma unroll
        for (int j = 0; j < 4; ++j)
#pragma unroll
            for (int r = 0; r < 4; ++r) acc[i][j][r] = 0.f;

    auto prefetch = [&](int st, int kt) {
        u32 b = sbase + st * 32768;
        size_t ko = (size_t)kt * 64;  // 32 bf16 = 64B
        cpa16(b + d0,         pAh0 + ko); cpa16(b + d1,         pAh1 + ko);
        cpa16(b + 8192 + d0,  pAl0 + ko); cpa16(b + 8192 + d1,  pAl1 + ko);
        cpa16(b + 16384 + d0, pWh0 + ko); cpa16(b + 16384 + d1, pWh1 + ko);
        cpa16(b + 24576 + d0, pWl0 + ko); cpa16(b + 24576 + d1, pWl1 + ko);
    };

    prefetch(0, 0); CP_COMMIT;
    prefetch(1, 1); CP_COMMIT;

    const int KT = K / 32;
    int stage = 0;
    for (int kt = 0; kt < KT; ++kt) {
        if (kt + 1 < KT) { CP_WAIT1; } else { CP_WAIT0; }
        __syncthreads();   // single barrier per iteration (3-stage ring makes 2nd redundant)
        if (kt + 2 < KT) {
            int ps = stage + 2; if (ps >= 3) ps -= 3;
            prefetch(ps, kt + 2); CP_COMMIT;
        }
        u32 base = sbase + stage * 32768;
#pragma unroll
        for (int s = 0; s < 2; ++s) {
            u32 bh[2][4], bl_[2][4];
#pragma unroll
            for (int jg = 0; jg < 2; ++jg) {
                ldsm4(bh[jg], base + 16384 + offB[jg][s]);
                ldsm4(bl_[jg], base + 24576 + offB[jg][s]);
            }
            u32 af[4][4];
#pragma unroll
            for (int i = 0; i < 4; ++i) ldsm4(af[i], base + offA[i][s]);
#pragma unroll
            for (int i = 0; i < 4; ++i)
#pragma unroll
                for (int j = 0; j < 4; ++j) {
                    int jg = j >> 1, sel = j & 1;
                    mma16816(acc[i][j], af[i], bh[jg][sel], bh[jg][sel + 2]);
                    mma16816(acc[i][j], af[i], bl_[jg][sel], bl_[jg][sel + 2]);
                }
#pragma unroll
            for (int i = 0; i < 4; ++i) ldsm4(af[i], base + 8192 + offA[i][s]);
#pragma unroll
            for (int i = 0; i < 4; ++i)
#pragma unroll
                for (int j = 0; j < 4; ++j) {
                    int jg = j >> 1, sel = j & 1;
                    mma16816(acc[i][j], af[i], bh[jg][sel], bh[jg][sel + 2]);
                }
        }
        if (++stage == 3) stage = 0;
    }

    const int g = lane >> 2, tg = lane & 3;
#pragma unroll
    for (int i = 0; i < 4; ++i) {
        int rA = m0 + 64 * wy + 16 * i + g;
        int rB = rA + 8;
#pragma unroll
        for (int j = 0; j < 4; ++j) {
            int col = n0 + 32 * wx + 8 * j + 2 * tg;
            float b0 = bias[col], b1 = bias[col + 1];
            float v0 = acc[i][j][0] + b0, v1 = acc[i][j][1] + b1;
            float v2 = acc[i][j][2] + b0, v3 = acc[i][j][3] + b1;
            if (splitOut) {
                u32 h, l;
                split_pair(v0, v1, h, l);
                *(u32*)(Ch + (size_t)rA * N + col) = h;
                *(u32*)(Cl + (size_t)rA * N + col) = l;
                split_pair(v2, v3, h, l);
                *(u32*)(Ch + (size_t)rB * N + col) = h;
                *(u32*)(Cl + (size_t)rB * N + col) = l;
            } else {
                *(float2*)(Cf + (size_t)rA * N + col) = make_float2(v0, v1);
                *(float2*)(Cf + (size_t)rB * N + col) = make_float2(v2, v3);
            }
        }
    }
}

// ---------------- block-sparse flash attention: 2 q-blocks per CTA ----------------
// 256 threads, 8 warps: warps 0-3 -> qb=2*bx (16-row strips), warps 4-7 -> qb=2*bx+1.
// CTA iterates the UNION of the two block masks; warps skip non-owned blocks.
__global__ __launch_bounds__(256) void attn_bs(
    const __nv_bfloat16* __restrict__ Qh, const __nv_bfloat16* __restrict__ Ql,
    const __nv_bfloat16* __restrict__ Kh, const __nv_bfloat16* __restrict__ Kl,
    const __nv_bfloat16* __restrict__ Vh, const __nv_bfloat16* __restrict__ Vl,
    __nv_bfloat16* __restrict__ Oh, __nv_bfloat16* __restrict__ Ol)
{
    extern __shared__ char smraw[];
    const u32 sb = smem_u32(smraw);
    const int t = threadIdx.x;
    const int lane = t & 31, warp = t >> 5;
    const int qpair = blockIdx.x;
    const int b = blockIdx.y >> 4, h = blockIdx.y & 15;
    const size_t gbase = (size_t)b * SEQN * EMB + (size_t)h * HD;
    const int qsel = warp >> 2, wq = warp & 3;
    const int myqb = 2 * qpair + qsel;
    const int lr = lane & 15, lc = lane >> 4;
    const int g = lane >> 2, tg = lane & 3;

    // Q load: 128 rows x 128B, hi+lo = 2048 chunks of 16B over 256 threads
#pragma unroll
    for (int it = 0; it < 8; ++it) {
        int id = t + 256 * it;
        int mat = id >> 10;          // 0 = Qh, 1 = Ql
        int cid = id & 1023;
        int row = cid >> 3, c = cid & 7;
        u32 dst = sb + mat * 16384 + swzA((u32)(row * 128 + c * 16));
        const __nv_bfloat16* srcb = mat ? Ql : Qh;
        const char* src = (const char*)(srcb + gbase + (size_t)(2 * qpair * 64 + row) * EMB) + c * 16;
        cpa16(dst, src);
    }

    const __nv_bfloat16* kvsrc[4] = { Kh, Kl, Vh, Vl };
    auto loadKV = [&](int buf, int kb) {
#pragma unroll
        for (int it = 0; it < 8; ++it) {
            int id = t + 256 * it;
            int mat = id >> 9;        // 0=Kh 1=Kl 2=Vh 3=Vl
            int cid = id & 511;
            int row = cid >> 3, c = cid & 7;
            u32 dst = sb + 32768 + buf * 32768 + mat * 8192 + swzA((u32)(row * 128 + c * 16));
            const char* src = (const char*)(kvsrc[mat] + gbase + (size_t)(kb * 64 + row) * EMB) + c * 16;
            cpa16(dst, src);
        }
    };

    const unsigned own = g_blockmask[myqb];
    unsigned rem = g_blockmask[2 * qpair] | g_blockmask[2 * qpair + 1];
    int kb = __ffs(rem) - 1; rem &= rem - 1;
    loadKV(0, kb); CP_COMMIT;

    u32 offQ[4];
#pragma unroll
    for (int c = 0; c < 4; ++c)
        offQ[c] = swzA((u32)((qsel * 64 + 16 * wq + lr) * 128 + (2 * c + lc) * 16));

    u32 qh[4][4], ql_[4][4];
    float o[8][4];
#pragma unroll
    for (int nt = 0; nt < 8; ++nt)
#pragma unroll
        for (int r = 0; r < 4; ++r) o[nt][r] = 0.f;
    float mrow0 = -INFINITY, mrow1 = -INFINITY, lrow0 = 0.f, lrow1 = 0.f;

    bool qloaded = false;
    int buf = 0;

    while (kb >= 0) {
        int nxt = rem ? (__ffs(rem) - 1) : -1;
        if (nxt >= 0) { rem &= rem - 1; loadKV(buf ^ 1, nxt); CP_COMMIT; CP_WAIT1; }
        else { CP_WAIT0; }
        __syncthreads();

        if (!qloaded) {
            qloaded = true;
#pragma unroll
            for (int c = 0; c < 4; ++c) {
                ldsm4(qh[c], sb + offQ[c]);
                ldsm4(ql_[c], sb + 16384 + offQ[c]);
            }
        }

        if ((own >> kb) & 1u) {
            u32 kvb = sb + 32768 + buf * 32768;

            float s[8][4];
#pragma unroll
            for (int nt = 0; nt < 8; ++nt)
#pragma unroll
                for (int r = 0; r < 4; ++r) s[nt][r] = 0.f;
#pragma unroll
            for (int c = 0; c < 4; ++c) {
#pragma unroll
                for (int jg = 0; jg < 4; ++jg) {
                    u32 off = swzA((u32)((16 * jg + lr) * 128 + (2 * c + lc) * 16));
                    u32 kh4[4], kl4[4];
                    ldsm4(kh4, kvb + off);
                    ldsm4(kl4, kvb + 8192 + off);
#pragma unroll
                    for (int sel = 0; sel < 2; ++sel) {
                        int nt = 2 * jg + sel;
                        mma16816(s[nt], qh[c], kh4[sel], kh4[sel + 2]);
                        mma16816(s[nt], qh[c], kl4[sel], kl4[sel + 2]);
                        mma16816(s[nt], ql_[c], kh4[sel], kh4[sel + 2]);
                    }
                }
            }

            float mx0 = -INFINITY, mx1 = -INFINITY;
#pragma unroll
            for (int nt = 0; nt < 8; ++nt) {
                s[nt][0] *= 0.125f; s[nt][1] *= 0.125f; s[nt][2] *= 0.125f; s[nt][3] *= 0.125f;
                mx0 = fmaxf(mx0, fmaxf(s[nt][0], s[nt][1]));
                mx1 = fmaxf(mx1, fmaxf(s[nt][2], s[nt][3]));
            }
            mx0 = fmaxf(mx0, __shfl_xor_sync(0xffffffffu, mx0, 1, 4));
            mx0 = fmaxf(mx0, __shfl_xor_sync(0xffffffffu, mx0, 2, 4));
            mx1 = fmaxf(mx1, __shfl_xor_sync(0xffffffffu, mx1, 1, 4));
            mx1 = fmaxf(mx1, __shfl_xor_sync(0xffffffffu, mx1, 2, 4));
            float mn0 = fmaxf(mrow0, mx0), mn1 = fmaxf(mrow1, mx1);
            float a0 = __expf(mrow0 - mn0), a1 = __expf(mrow1 - mn1);
            float sum0 = 0.f, sum1 = 0.f;
#pragma unroll
            for (int nt = 0; nt < 8; ++nt) {
                s[nt][0] = __expf(s[nt][0] - mn0); s[nt][1] = __expf(s[nt][1] - mn0);
                s[nt][2] = __expf(s[nt][2] - mn1); s[nt][3] = __expf(s[nt][3] - mn1);
                sum0 += s[nt][0] + s[nt][1];
                sum1 += s[nt][2] + s[nt][3];
            }
            sum0 += __shfl_xor_sync(0xffffffffu, sum0, 1, 4);
            sum0 += __shfl_xor_sync(0xffffffffu, sum0, 2, 4);
            sum1 += __shfl_xor_sync(0xffffffffu, sum1, 1, 4);
            sum1 += __shfl_xor_sync(0xffffffffu, sum1, 2, 4);
            lrow0 = lrow0 * a0 + sum0; lrow1 = lrow1 * a1 + sum1;
            mrow0 = mn0; mrow1 = mn1;
#pragma unroll
            for (int nt = 0; nt < 8; ++nt) {
                o[nt][0] *= a0; o[nt][1] *= a0; o[nt][2] *= a1; o[nt][3] *= a1;
            }

            u32 ph[8][2], pl[8][2];
#pragma unroll
            for (int nt = 0; nt < 8; ++nt) {
                split_pair(s[nt][0], s[nt][1], ph[nt][0], pl[nt][0]);
                split_pair(s[nt][2], s[nt][3], ph[nt][1], pl[nt][1]);
            }

#pragma unroll
            for (int c = 0; c < 4; ++c) {
                u32 aph[4] = { ph[2 * c][0], ph[2 * c][1], ph[2 * c + 1][0], ph[2 * c + 1][1] };
                u32 apl[4] = { pl[2 * c][0], pl[2 * c][1], pl[2 * c + 1][0], pl[2 * c + 1][1] };
#pragma unroll
                for (int jg = 0; jg < 4; ++jg) {
                    u32 off = swzA((u32)((16 * c + lr) * 128 + (2 * jg + lc) * 16));
                    u32 vh4[4], vl4[4];
                    ldsm4t(vh4, kvb + 16384 + off);
                    ldsm4t(vl4, kvb + 24576 + off);
#pragma unroll
                    for (int sel = 0; sel < 2; ++sel) {
                        int nt = 2 * jg + sel;
                        mma16816(o[nt], aph, vh4[2 * sel], vh4[2 * sel + 1]);
                        mma16816(o[nt], aph, vl4[2 * sel], vl4[2 * sel + 1]);
                        mma16816(o[nt], apl, vh4[2 * sel], vh4[2 * sel + 1]);
                    }
                }
            }
        }

        __syncthreads();
        buf ^= 1;
        kb = nxt;
    }

    float inv0 = 1.f / lrow0, inv1 = 1.f / lrow1;
    int row0 = myqb * 64 + 16 * wq + g;
    int row1 = row0 + 8;
#pragma unroll
    for (int nt = 0; nt < 8; ++nt) {
        int col = 8 * nt + 2 * tg;
        size_t i0 = gbase + (size_t)row0 * EMB + col;
        size_t i1 = gbase + (size_t)row1 * EMB + col;
        u32 hh, ll;
        split_pair(o[nt][0] * inv0, o[nt][1] * inv0, hh, ll);
        *(u32*)(Oh + i0) = hh; *(u32*)(Ol + i0) = ll;
        split_pair(o[nt][2] * inv1, o[nt][3] * inv1, hh, ll);
        *(u32*)(Oh + i1) = hh; *(u32*)(Ol + i1) = ll;
    }
}

// ---------------- launcher ----------------
extern "C" void kernel_launch(void* const* d_in, const int* in_sizes, int n_in,
                              void* d_out, int out_size)
{
    (void)in_sizes; (void)n_in; (void)out_size;
    const float* hs = (const float*)d_in[0];
    const float* wq = (const float*)d_in[1];
    const float* bq = (const float*)d_in[2];
    const float* wk = (const float*)d_in[3];
    const float* bk = (const float*)d_in[4];
    const float* wv = (const float*)d_in[5];
    const float* bv = (const float*)d_in[6];
    const float* wo = (const float*)d_in[7];
    const float* bo = (const float*)d_in[8];
    float* out = (float*)d_out;

    __nv_bfloat16 *hs_h, *hs_l, *wq_h, *wq_l, *wk_h, *wk_l, *wv_h, *wv_l, *wo_h, *wo_l;
    __nv_bfloat16 *q_h, *q_l, *k_h, *k_l, *v_h, *v_l, *c_h, *c_l;
    cudaGetSymbolAddress((void**)&hs_h, g_hs_h); cudaGetSymbolAddress((void**)&hs_l, g_hs_l);
    cudaGetSymbolAddress((void**)&wq_h, g_wq_h); cudaGetSymbolAddress((void**)&wq_l, g_wq_l);
    cudaGetSymbolAddress((void**)&wk_h, g_wk_h); cudaGetSymbolAddress((void**)&wk_l, g_wk_l);
    cudaGetSymbolAddress((void**)&wv_h, g_wv_h); cudaGetSymbolAddress((void**)&wv_l, g_wv_l);
    cudaGetSymbolAddress((void**)&wo_h, g_wo_h); cudaGetSymbolAddress((void**)&wo_l, g_wo_l);
    cudaGetSymbolAddress((void**)&q_h, g_q_h);   cudaGetSymbolAddress((void**)&q_l, g_q_l);
    cudaGetSymbolAddress((void**)&k_h, g_k_h);   cudaGetSymbolAddress((void**)&k_l, g_k_l);
    cudaGetSymbolAddress((void**)&v_h, g_v_h);   cudaGetSymbolAddress((void**)&v_l, g_v_l);
    cudaGetSymbolAddress((void**)&c_h, g_c_h);   cudaGetSymbolAddress((void**)&c_l, g_c_l);

    cudaFuncSetAttribute(gemm_qkv, cudaFuncAttributeMaxDynamicSharedMemorySize, 98304);
    cudaFuncSetAttribute(attn_bs, cudaFuncAttributeMaxDynamicSharedMemorySize, 98304);

    {
        int n4hs = MROWS * EMB / 4;
        int n4w = EMB * EMB / 4;
        split_f32<<<n4hs / 256, 256>>>((const float4*)hs, hs_h, hs_l, n4hs);          // 0
        split_w4<<<dim3(n4w / 256, 4), 256>>>((const float4*)wq, (const float4*)wk,
            (const float4*)wv, (const float4*)wo,
            wq_h, wq_l, wk_h, wk_l, wv_h, wv_l, wo_h, wo_l, n4w);                     // 1
    }
    init_mask_kernel<<<1, 32>>>();                                                    // 2

    dim3 gqkv(EMB / 128, MROWS / 128, 3); // (8, 32, 3)
    gemm_qkv<<<gqkv, 256, 98304>>>(hs_h, hs_l,
        wq_h, wq_l, bq, wk_h, wk_l, bk, wv_h, wv_l, bv,
        q_h, q_l, k_h, k_l, v_h, v_l, nullptr, 1);                                    // 3

    noop_kernel<<<1, 32>>>();                                                         // 4 (spacer)

    attn_bs<<<dim3(NB / 2, BATCH * NH), 256, 98304>>>(q_h, q_l, k_h, k_l, v_h, v_l, c_h, c_l); // 5 <- ncu

    dim3 go(EMB / 128, MROWS / 128, 1);
    gemm_qkv<<<go, 256, 98304>>>(c_h, c_l,
        wo_h, wo_l, bo, wo_h, wo_l, bo, wo_h, wo_l, bo,
        nullptr, nullptr, nullptr, nullptr, nullptr, nullptr, out, 0);                // 6
}

// round 13
// speedup vs baseline: 1.0213x; 1.0213x over previous
#include <cuda_runtime.h>
#include <cuda_bf16.h>
#include <math.h>

typedef unsigned u32;
typedef unsigned long long u64;

#define BATCH 2
#define SEQN 2048
#define EMB 1024
#define NH 16
#define HD 64
#define NB 32
#define MROWS (BATCH*SEQN)   // 4096

// ---------------- scratch: static device globals ----------------
__device__ __nv_bfloat16 g_hs_h[MROWS*EMB], g_hs_l[MROWS*EMB];
__device__ __nv_bfloat16 g_wq_h[EMB*EMB], g_wq_l[EMB*EMB];
__device__ __nv_bfloat16 g_wk_h[EMB*EMB], g_wk_l[EMB*EMB];
__device__ __nv_bfloat16 g_wv_h[EMB*EMB], g_wv_l[EMB*EMB];
__device__ __nv_bfloat16 g_wo_h[EMB*EMB], g_wo_l[EMB*EMB];
__device__ __nv_bfloat16 g_q_h[MROWS*EMB], g_q_l[MROWS*EMB];
__device__ __nv_bfloat16 g_k_h[MROWS*EMB], g_k_l[MROWS*EMB];
__device__ __nv_bfloat16 g_v_h[MROWS*EMB], g_v_l[MROWS*EMB];
__device__ __nv_bfloat16 g_c_h[MROWS*EMB], g_c_l[MROWS*EMB];
__device__ unsigned g_blockmask[NB];

// ---------------- asm helpers ----------------
__device__ __forceinline__ u32 smem_u32(const void* p) {
    return (u32)__cvta_generic_to_shared(p);
}
__device__ __forceinline__ void ldsm4(u32 a[4], u32 addr) {
    asm volatile("ldmatrix.sync.aligned.m8n8.x4.shared.b16 {%0,%1,%2,%3}, [%4];"
        : "=r"(a[0]), "=r"(a[1]), "=r"(a[2]), "=r"(a[3]) : "r"(addr));
}
__device__ __forceinline__ void ldsm4t(u32 a[4], u32 addr) {
    asm volatile("ldmatrix.sync.aligned.m8n8.x4.trans.shared.b16 {%0,%1,%2,%3}, [%4];"
        : "=r"(a[0]), "=r"(a[1]), "=r"(a[2]), "=r"(a[3]) : "r"(addr));
}
__device__ __forceinline__ void mma16816(float d[4], const u32 a[4], u32 b0, u32 b1) {
    asm volatile("mma.sync.aligned.m16n8k16.row.col.f32.bf16.bf16.f32 "
        "{%0,%1,%2,%3},{%4,%5,%6,%7},{%8,%9},{%0,%1,%2,%3};"
        : "+f"(d[0]), "+f"(d[1]), "+f"(d[2]), "+f"(d[3])
        : "r"(a[0]), "r"(a[1]), "r"(a[2]), "r"(a[3]), "r"(b0), "r"(b1));
}
__device__ __forceinline__ void cpa16(u32 dst, const void* src) {
    asm volatile("cp.async.cg.shared.global [%0], [%1], 16;" :: "r"(dst), "l"(src));
}
#define CP_COMMIT asm volatile("cp.async.commit_group;" ::: "memory")
#define CP_WAIT0  asm volatile("cp.async.wait_group 0;" ::: "memory")
#define CP_WAIT1  asm volatile("cp.async.wait_group 1;" ::: "memory")

// swizzles: 64B-row tiles (GEMM) and 128B-row tiles (attention)
__device__ __forceinline__ u32 swzG(u32 off) { return off ^ (((off >> 7) & 3u) << 4); }
__device__ __forceinline__ u32 swzA(u32 off) { return off ^ ((off >> 3) & 0x70u); }

// split two fp32 into packed bf16 hi-pair and lo-pair
__device__ __forceinline__ void split_pair(float x0, float x1, u32& h, u32& l) {
    __nv_bfloat16 h0 = __float2bfloat16(x0), h1 = __float2bfloat16(x1);
    float r0 = x0 - __bfloat162float(h0), r1 = x1 - __bfloat162float(h1);
    __nv_bfloat16 l0 = __float2bfloat16(r0), l1 = __float2bfloat16(r1);
    __nv_bfloat162 hp; hp.x = h0; hp.y = h1;
    __nv_bfloat162 lp; lp.x = l0; lp.y = l1;
    h = *reinterpret_cast<u32*>(&hp);
    l = *reinterpret_cast<u32*>(&lp);
}

// ---------------- MT19937 mask init, warp-parallel twist ----------------
#define NGEN_BLOCKS 4
__global__ void init_mask_kernel() {
    __shared__ unsigned mt[624];
    __shared__ unsigned rnd[NGEN_BLOCKS * 624];
    const int t = threadIdx.x;

    if (t == 0) {
        unsigned s = 0u;
        for (int i = 0; i < 624; ++i) { mt[i] = s; s = 1812433253u * (s ^ (s >> 30)) + (unsigned)i + 1u; }
    }
    __syncwarp();

    auto twist_range = [&](int lo, int hi) {
        for (int base = lo; base < hi; base += 32) {
            int i = base + t;
            unsigned nv = 0; bool act = (i < hi);
            if (act) {
                unsigned y = (mt[i] & 0x80000000u) | (mt[(i + 1) % 624] & 0x7fffffffu);
                nv = mt[(i + 397) % 624] ^ (y >> 1) ^ ((y & 1u) ? 0x9908b0dfu : 0u);
            }
            __syncwarp();
            if (act) mt[i] = nv;
            __syncwarp();
        }
    };

    for (int blk = 0; blk < NGEN_BLOCKS; ++blk) {
        twist_range(0, 227);
        twist_range(227, 454);
        twist_range(454, 624);
        for (int i = t; i < 624; i += 32) {
            unsigned y = mt[i];
            y ^= y >> 11; y ^= (y << 7) & 0x9d2c5680u; y ^= (y << 15) & 0xefc60000u; y ^= y >> 18;
            rnd[blk * 624 + i] = y;
        }
        __syncwarp();
    }

    if (t != 0) return;

    int idx = 0;
    auto next32 = [&]() -> unsigned { return rnd[idx++]; };
    auto rand_interval = [&](unsigned maxv) -> unsigned {
        if (maxv == 0u) return 0u;
        unsigned mask = maxv;
        mask |= mask >> 1; mask |= mask >> 2; mask |= mask >> 4; mask |= mask >> 8; mask |= mask >> 16;
        unsigned v;
        do { v = next32() & mask; } while (v > maxv);
        return v;
    };
    unsigned bm[NB];
    bm[0] = 0xffffffffu;
    for (int qb = 1; qb < NB; ++qb) {
        unsigned m = 1u;
        int lo = qb - 3; if (lo < 0) lo = 0;
        int hi = qb + 3; if (hi > NB - 1) hi = NB - 1;
        for (int kb = lo; kb <= hi; ++kb) m |= (1u << kb);
        bm[qb] = m;
    }
    for (int b = 1; b < NB; ++b) {
        int avail[NB]; int pop = 0;
        for (int x = 1; x < NB; ++x)
            if ((x - b > 3) || (b - x > 3)) avail[pop++] = x;
        if (pop == 0) continue;
        int perm[NB];
        for (int i = 0; i < pop; ++i) perm[i] = i;
        for (int i = pop - 1; i > 0; --i) {
            unsigned j = rand_interval((unsigned)i);
            int tmp = perm[i]; perm[i] = perm[j]; perm[j] = tmp;
        }
        int take = pop < 3 ? pop : 3;
        for (int tsel = 0; tsel < take; ++tsel) bm[b] |= (1u << avail[perm[tsel]]);
    }
    for (int i = 0; i < NB; ++i) g_blockmask[i] = bm[i];
}

__global__ void noop_kernel() {}

// ---------------- fp32 -> bf16 hi/lo splits ----------------
__global__ void split_f32(const float4* __restrict__ src,
                          __nv_bfloat16* __restrict__ h, __nv_bfloat16* __restrict__ l, int n4)
{
    int i = blockIdx.x * blockDim.x + threadIdx.x;
    if (i >= n4) return;
    float4 v = src[i];
    u32 h0, l0, h1, l1;
    split_pair(v.x, v.y, h0, l0);
    split_pair(v.z, v.w, h1, l1);
    u32* hp = (u32*)h + 2 * i;
    u32* lp = (u32*)l + 2 * i;
    hp[0] = h0; hp[1] = h1;
    lp[0] = l0; lp[1] = l1;
}

__global__ void split_w4(const float4* w0, const float4* w1, const float4* w2, const float4* w3,
                         __nv_bfloat16* h0, __nv_bfloat16* l0, __nv_bfloat16* h1, __nv_bfloat16* l1,
                         __nv_bfloat16* h2, __nv_bfloat16* l2, __nv_bfloat16* h3, __nv_bfloat16* l3,
                         int n4)
{
    int i = blockIdx.x * blockDim.x + threadIdx.x;
    if (i >= n4) return;
    int sel = blockIdx.y;
    const float4* src = (sel == 0) ? w0 : (sel == 1) ? w1 : (sel == 2) ? w2 : w3;
    __nv_bfloat16* h = (sel == 0) ? h0 : (sel == 1) ? h1 : (sel == 2) ? h2 : h3;
    __nv_bfloat16* l = (sel == 0) ? l0 : (sel == 1) ? l1 : (sel == 2) ? l2 : l3;
    float4 v = src[i];
    u32 a0, b0, a1, b1;
    split_pair(v.x, v.y, a0, b0);
    split_pair(v.z, v.w, a1, b1);
    u32* hp = (u32*)h + 2 * i;
    u32* lp = (u32*)l + 2 * i;
    hp[0] = a0; hp[1] = a1;
    lp[0] = b0; lp[1] = b1;
}

// ---------------- bf16-split GEMM, 3-stage ring, 1 sync/iter, 2 CTAs/SM ----------------
// CTA 128x128, BK=32, 256 threads (8 warps, 2x4), warp tile 64x32, acc fp32.
__global__ __launch_bounds__(256, 2) void gemm_qkv(
    const __nv_bfloat16* __restrict__ Ah, const __nv_bfloat16* __restrict__ Al,
    const __nv_bfloat16* __restrict__ W0h, const __nv_bfloat16* __restrict__ W0l, const float* __restrict__ b0v,
    const __nv_bfloat16* __restrict__ W1h, const __nv_bfloat16* __restrict__ W1l, const float* __restrict__ b1v,
    const __nv_bfloat16* __restrict__ W2h, const __nv_bfloat16* __restrict__ W2l, const float* __restrict__ b2v,
    __nv_bfloat16* __restrict__ C0h, __nv_bfloat16* __restrict__ C0l,
    __nv_bfloat16* __restrict__ C1h, __nv_bfloat16* __restrict__ C1l,
    __nv_bfloat16* __restrict__ C2h, __nv_bfloat16* __restrict__ C2l,
    float* __restrict__ Cf, int splitOut)
{
    extern __shared__ char smraw[];
    const u32 sbase = smem_u32(smraw);
    const int t = threadIdx.x;
    const int lane = t & 31, warp = t >> 5;
    const int wy = warp >> 2, wx = warp & 3;
    const int m0 = blockIdx.y * 128, n0 = blockIdx.x * 128;
    const int z = blockIdx.z;
    const int K = EMB, N = EMB;

    const __nv_bfloat16* Wh = (z == 0) ? W0h : (z == 1) ? W1h : W2h;
    const __nv_bfloat16* Wl = (z == 0) ? W0l : (z == 1) ? W1l : W2l;
    const float* bias       = (z == 0) ? b0v : (z == 1) ? b1v : b2v;
    __nv_bfloat16* Ch       = (z == 0) ? C0h : (z == 1) ? C1h : C2h;
    __nv_bfloat16* Cl       = (z == 0) ? C0l : (z == 1) ? C1l : C2l;

    const int cch = t & 3;
    const int r0 = t >> 2;
    const u32 d0 = swzG((u32)(r0 * 64 + cch * 16));
    const u32 d1 = swzG((u32)((r0 + 64) * 64 + cch * 16));
    const char* pAh0 = (const char*)(Ah + (size_t)(m0 + r0) * K) + cch * 16;
    const char* pAh1 = (const char*)(Ah + (size_t)(m0 + r0 + 64) * K) + cch * 16;
    const char* pAl0 = (const char*)(Al + (size_t)(m0 + r0) * K) + cch * 16;
    const char* pAl1 = (const char*)(Al + (size_t)(m0 + r0 + 64) * K) + cch * 16;
    const char* pWh0 = (const char*)(Wh + (size_t)(n0 + r0) * K) + cch * 16;
    const char* pWh1 = (const char*)(Wh + (size_t)(n0 + r0 + 64) * K) + cch * 16;
    const char* pWl0 = (const char*)(Wl + (size_t)(n0 + r0) * K) + cch * 16;
    const char* pWl1 = (const char*)(Wl + (size_t)(n0 + r0 + 64) * K) + cch * 16;

    const int lr = lane & 15, lc = lane >> 4;
    u32 offA[4][2], offB[2][2];
#pragma unroll
    for (int i = 0; i < 4; ++i)
#pragma unroll
        for (int s = 0; s < 2; ++s)
            offA[i][s] = swzG((u32)((64 * wy + 16 * i + lr) * 64 + (2 * s + lc) * 16));
#pragma unroll
    for (int jg = 0; jg < 2; ++jg)
#pragma unroll
        for (int s = 0; s < 2; ++s)
            offB[jg][s] = swzG((u32)((32 * wx + 16 * jg + lr) * 64 + (2 * s + lc) * 16));

    float acc[4][4][4];
#pragma unroll
    for (int i = 0; i < 4; ++i)
#pragma unroll
        for (int j = 0; j < 4; ++j)
#pragma unroll
            for (int r = 0; r < 4; ++r) acc[i][j][r] = 0.f;

    auto prefetch = [&](int st, int kt) {
        u32 b = sbase + st * 32768;
        size_t ko = (size_t)kt * 64;  // 32 bf16 = 64B
        cpa16(b + d0,         pAh0 + ko); cpa16(b + d1,         pAh1 + ko);
        cpa16(b + 8192 + d0,  pAl0 + ko); cpa16(b + 8192 + d1,  pAl1 + ko);
        cpa16(b + 16384 + d0, pWh0 + ko); cpa16(b + 16384 + d1, pWh1 + ko);
        cpa16(b + 24576 + d0, pWl0 + ko); cpa16(b + 24576 + d1, pWl1 + ko);
    };

    prefetch(0, 0); CP_COMMIT;
    prefetch(1, 1); CP_COMMIT;

    const int KT = K / 32;
    int stage = 0;
    for (int kt = 0; kt < KT; ++kt) {
        if (kt + 1 < KT) { CP_WAIT1; } else { CP_WAIT0; }
        __syncthreads();   // single barrier per iteration (3-stage ring makes 2nd redundant)
        if (kt + 2 < KT) {
            int ps = stage + 2; if (ps >= 3) ps -= 3;
            prefetch(ps, kt + 2); CP_COMMIT;
        }
        u32 base = sbase + stage * 32768;
#pragma unroll
        for (int s = 0; s < 2; ++s) {
            u32 bh[2][4], bl_[2][4];
#pragma unroll
            for (int jg = 0; jg < 2; ++jg) {
                ldsm4(bh[jg], base + 16384 + offB[jg][s]);
                ldsm4(bl_[jg], base + 24576 + offB[jg][s]);
            }
            u32 af[4][4];
#pragma unroll
            for (int i = 0; i < 4; ++i) ldsm4(af[i], base + offA[i][s]);
#pragma unroll
            for (int i = 0; i < 4; ++i)
#pragma unroll
                for (int j = 0; j < 4; ++j) {
                    int jg = j >> 1, sel = j & 1;
                    mma16816(acc[i][j], af[i], bh[jg][sel], bh[jg][sel + 2]);
                    mma16816(acc[i][j], af[i], bl_[jg][sel], bl_[jg][sel + 2]);
                }
#pragma unroll
            for (int i = 0; i < 4; ++i) ldsm4(af[i], base + 8192 + offA[i][s]);
#pragma unroll
            for (int i = 0; i < 4; ++i)
#pragma unroll
                for (int j = 0; j < 4; ++j) {
                    int jg = j >> 1, sel = j & 1;
                    mma16816(acc[i][j], af[i], bh[jg][sel], bh[jg][sel + 2]);
                }
        }
        if (++stage == 3) stage = 0;
    }

    const int g = lane >> 2, tg = lane & 3;
#pragma unroll
    for (int i = 0; i < 4; ++i) {
        int rA = m0 + 64 * wy + 16 * i + g;
        int rB = rA + 8;
#pragma unroll
        for (int j = 0; j < 4; ++j) {
            int col = n0 + 32 * wx + 8 * j + 2 * tg;
            float b0 = bias[col], b1 = bias[col + 1];
            float v0 = acc[i][j][0] + b0, v1 = acc[i][j][1] + b1;
            float v2 = acc[i][j][2] + b0, v3 = acc[i][j][3] + b1;
            if (splitOut) {
                u32 h, l;
                split_pair(v0, v1, h, l);
                *(u32*)(Ch + (size_t)rA * N + col) = h;
                *(u32*)(Cl + (size_t)rA * N + col) = l;
                split_pair(v2, v3, h, l);
                *(u32*)(Ch + (size_t)rB * N + col) = h;
                *(u32*)(Cl + (size_t)rB * N + col) = l;
            } else {
                *(float2*)(Cf + (size_t)rA * N + col) = make_float2(v0, v1);
                *(float2*)(Cf + (size_t)rB * N + col) = make_float2(v2, v3);
            }
        }
    }
}

// ---------------- block-sparse flash attention (mma.sync, bf16-split) ----------------
// 128 threads, 1 q-block per CTA. smem = 64KB: KV buf0 [0,32K), buf1 [32K,64K).
// Q is loaded INTO buf1's slots, fragments extracted before buf1 is first written
// (Q smem is dead after the one-time ldsm), enabling 3 CTAs/SM.
__global__ __launch_bounds__(128, 3) void attn_bs(
    const __nv_bfloat16* __restrict__ Qh, const __nv_bfloat16* __restrict__ Ql,
    const __nv_bfloat16* __restrict__ Kh, const __nv_bfloat16* __restrict__ Kl,
    const __nv_bfloat16* __restrict__ Vh, const __nv_bfloat16* __restrict__ Vl,
    __nv_bfloat16* __restrict__ Oh, __nv_bfloat16* __restrict__ Ol)
{
    extern __shared__ char smraw[];
    const u32 sb = smem_u32(smraw);
    const int t = threadIdx.x;
    const int lane = t & 31, warp = t >> 5;
    const int qb = blockIdx.x;
    const int b = blockIdx.y >> 4, h = blockIdx.y & 15;
    const size_t gbase = (size_t)b * SEQN * EMB + (size_t)h * HD;
    const int lr = lane & 15, lc = lane >> 4;
    const int g = lane >> 2, tg = lane & 3;

    // Q load into buf1 region (slots 0=Qh, 1=Ql): 1024 chunks of 16B over 128 threads
#pragma unroll
    for (int it = 0; it < 8; ++it) {
        int id = t + 128 * it;
        int mat = it >> 2;
        int cid = id & 511;
        int row = cid >> 3, c = cid & 7;
        u32 dst = sb + 32768 + mat * 8192 + swzA((u32)(row * 128 + c * 16));
        const __nv_bfloat16* srcb = mat ? Ql : Qh;
        const char* src = (const char*)(srcb + gbase + (size_t)(qb * 64 + row) * EMB) + c * 16;
        cpa16(dst, src);
    }

    const __nv_bfloat16* kvsrc[4] = { Kh, Kl, Vh, Vl };
    auto loadKV = [&](int buf, int kb) {
#pragma unroll
        for (int it = 0; it < 16; ++it) {
            int id = t + 128 * it;
            int mat = it >> 2;
            int cid = id & 511;
            int row = cid >> 3, c = cid & 7;
            u32 dst = sb + buf * 32768 + mat * 8192 + swzA((u32)(row * 128 + c * 16));
            const char* src = (const char*)(kvsrc[mat] + gbase + (size_t)(kb * 64 + row) * EMB) + c * 16;
            cpa16(dst, src);
        }
    };

    unsigned rem = g_blockmask[qb];
    int kb = __ffs(rem) - 1; rem &= rem - 1;
    loadKV(0, kb);
    CP_COMMIT;              // one group: Q + first KV block
    CP_WAIT0;
    __syncthreads();

    // extract Q fragments from buf1 region (then the region is dead)
    u32 qh[4][4], ql_[4][4];
#pragma unroll
    for (int c = 0; c < 4; ++c) {
        u32 offQ = swzA((u32)((16 * warp + lr) * 128 + (2 * c + lc) * 16));
        ldsm4(qh[c], sb + 32768 + offQ);
        ldsm4(ql_[c], sb + 32768 + 8192 + offQ);
    }
    __syncthreads();        // all warps done reading Q before buf1 is overwritten

    float o[8][4];
#pragma unroll
    for (int nt = 0; nt < 8; ++nt)
#pragma unroll
        for (int r = 0; r < 4; ++r) o[nt][r] = 0.f;
    float mrow0 = -INFINITY, mrow1 = -INFINITY, lrow0 = 0.f, lrow1 = 0.f;

    int buf = 0;
    bool first = true;

    while (kb >= 0) {
        int nxt = rem ? (__ffs(rem) - 1) : -1;
        if (nxt >= 0) { rem &= rem - 1; loadKV(buf ^ 1, nxt); CP_COMMIT; CP_WAIT1; }
        else { CP_WAIT0; }
        if (!first) __syncthreads();
        first = false;

        u32 kvb = sb + buf * 32768;

        float s[8][4];
#pragma unroll
        for (int nt = 0; nt < 8; ++nt)
#pragma unroll
            for (int r = 0; r < 4; ++r) s[nt][r] = 0.f;
#pragma unroll
        for (int c = 0; c < 4; ++c) {
#pragma unroll
            for (int jg = 0; jg < 4; ++jg) {
                u32 off = swzA((u32)((16 * jg + lr) * 128 + (2 * c + lc) * 16));
                u32 kh4[4], kl4[4];
                ldsm4(kh4, kvb + off);
                ldsm4(kl4, kvb + 8192 + off);
#pragma unroll
                for (int sel = 0; sel < 2; ++sel) {
                    int nt = 2 * jg + sel;
                    mma16816(s[nt], qh[c], kh4[sel], kh4[sel + 2]);
                    mma16816(s[nt], qh[c], kl4[sel], kl4[sel + 2]);
                    mma16816(s[nt], ql_[c], kh4[sel], kh4[sel + 2]);
                }
            }
        }

        float mx0 = -INFINITY, mx1 = -INFINITY;
#pragma unroll
        for (int nt = 0; nt < 8; ++nt) {
            s[nt][0] *= 0.125f; s[nt][1] *= 0.125f; s[nt][2] *= 0.125f; s[nt][3] *= 0.125f;
            mx0 = fmaxf(mx0, fmaxf(s[nt][0], s[nt][1]));
            mx1 = fmaxf(mx1, fmaxf(s[nt][2], s[nt][3]));
        }
        mx0 = fmaxf(mx0, __shfl_xor_sync(0xffffffffu, mx0, 1, 4));
        mx0 = fmaxf(mx0, __shfl_xor_sync(0xffffffffu, mx0, 2, 4));
        mx1 = fmaxf(mx1, __shfl_xor_sync(0xffffffffu, mx1, 1, 4));
        mx1 = fmaxf(mx1, __shfl_xor_sync(0xffffffffu, mx1, 2, 4));
        float mn0 = fmaxf(mrow0, mx0), mn1 = fmaxf(mrow1, mx1);
        float a0 = __expf(mrow0 - mn0), a1 = __expf(mrow1 - mn1);
        float sum0 = 0.f, sum1 = 0.f;
#pragma unroll
        for (int nt = 0; nt < 8; ++nt) {
            s[nt][0] = __expf(s[nt][0] - mn0); s[nt][1] = __expf(s[nt][1] - mn0);
            s[nt][2] = __expf(s[nt][2] - mn1); s[nt][3] = __expf(s[nt][3] - mn1);
            sum0 += s[nt][0] + s[nt][1];
            sum1 += s[nt][2] + s[nt][3];
        }
        sum0 += __shfl_xor_sync(0xffffffffu, sum0, 1, 4);
        sum0 += __shfl_xor_sync(0xffffffffu, sum0, 2, 4);
        sum1 += __shfl_xor_sync(0xffffffffu, sum1, 1, 4);
        sum1 += __shfl_xor_sync(0xffffffffu, sum1, 2, 4);
        lrow0 = lrow0 * a0 + sum0; lrow1 = lrow1 * a1 + sum1;
        mrow0 = mn0; mrow1 = mn1;
#pragma unroll
        for (int nt = 0; nt < 8; ++nt) {
            o[nt][0] *= a0; o[nt][1] *= a0; o[nt][2] *= a1; o[nt][3] *= a1;
        }

        u32 ph[8][2], pl[8][2];
#pragma unroll
        for (int nt = 0; nt < 8; ++nt) {
            split_pair(s[nt][0], s[nt][1], ph[nt][0], pl[nt][0]);
            split_pair(s[nt][2], s[nt][3], ph[nt][1], pl[nt][1]);
        }

#pragma unroll
        for (int c = 0; c < 4; ++c) {
            u32 aph[4] = { ph[2 * c][0], ph[2 * c][1], ph[2 * c + 1][0], ph[2 * c + 1][1] };
            u32 apl[4] = { pl[2 * c][0], pl[2 * c][1], pl[2 * c + 1][0], pl[2 * c + 1][1] };
#pragma unroll
            for (int jg = 0; jg < 4; ++jg) {
                u32 off = swzA((u32)((16 * c + lr) * 128 + (2 * jg + lc) * 16));
                u32 vh4[4], vl4[4];
                ldsm4t(vh4, kvb + 16384 + off);
                ldsm4t(vl4, kvb + 24576 + off);
#pragma unroll
                for (int sel = 0; sel < 2; ++sel) {
                    int nt = 2 * jg + sel;
                    mma16816(o[nt], aph, vh4[2 * sel], vh4[2 * sel + 1]);
                    mma16816(o[nt], aph, vl4[2 * sel], vl4[2 * sel + 1]);
                    mma16816(o[nt], apl, vh4[2 * sel], vh4[2 * sel + 1]);
                }
            }
        }

        __syncthreads();
        buf ^= 1;
        kb = nxt;
    }

    float inv0 = 1.f / lrow0, inv1 = 1.f / lrow1;
    int row0 = qb * 64 + 16 * warp + g;
    int row1 = row0 + 8;
#pragma unroll
    for (int nt = 0; nt < 8; ++nt) {
        int col = 8 * nt + 2 * tg;
        size_t i0 = gbase + (size_t)row0 * EMB + col;
        size_t i1 = gbase + (size_t)row1 * EMB + col;
        u32 hh, ll;
        split_pair(o[nt][0] * inv0, o[nt][1] * inv0, hh, ll);
        *(u32*)(Oh + i0) = hh; *(u32*)(Ol + i0) = ll;
        split_pair(o[nt][2] * inv1, o[nt][3] * inv1, hh, ll);
        *(u32*)(Oh + i1) = hh; *(u32*)(Ol + i1) = ll;
    }
}

// ---------------- launcher ----------------
extern "C" void kernel_launch(void* const* d_in, const int* in_sizes, int n_in,
                              void* d_out, int out_size)
{
    (void)in_sizes; (void)n_in; (void)out_size;
    const float* hs = (const float*)d_in[0];
    const float* wq = (const float*)d_in[1];
    const float* bq = (const float*)d_in[2];
    const float* wk = (const float*)d_in[3];
    const float* bk = (const float*)d_in[4];
    const float* wv = (const float*)d_in[5];
    const float* bv = (const float*)d_in[6];
    const float* wo = (const float*)d_in[7];
    const float* bo = (const float*)d_in[8];
    float* out = (float*)d_out;

    __nv_bfloat16 *hs_h, *hs_l, *wq_h, *wq_l, *wk_h, *wk_l, *wv_h, *wv_l, *wo_h, *wo_l;
    __nv_bfloat16 *q_h, *q_l, *k_h, *k_l, *v_h, *v_l, *c_h, *c_l;
    cudaGetSymbolAddress((void**)&hs_h, g_hs_h); cudaGetSymbolAddress((void**)&hs_l, g_hs_l);
    cudaGetSymbolAddress((void**)&wq_h, g_wq_h); cudaGetSymbolAddress((void**)&wq_l, g_wq_l);
    cudaGetSymbolAddress((void**)&wk_h, g_wk_h); cudaGetSymbolAddress((void**)&wk_l, g_wk_l);
    cudaGetSymbolAddress((void**)&wv_h, g_wv_h); cudaGetSymbolAddress((void**)&wv_l, g_wv_l);
    cudaGetSymbolAddress((void**)&wo_h, g_wo_h); cudaGetSymbolAddress((void**)&wo_l, g_wo_l);
    cudaGetSymbolAddress((void**)&q_h, g_q_h);   cudaGetSymbolAddress((void**)&q_l, g_q_l);
    cudaGetSymbolAddress((void**)&k_h, g_k_h);   cudaGetSymbolAddress((void**)&k_l, g_k_l);
    cudaGetSymbolAddress((void**)&v_h, g_v_h);   cudaGetSymbolAddress((void**)&v_l, g_v_l);
    cudaGetSymbolAddress((void**)&c_h, g_c_h);   cudaGetSymbolAddress((void**)&c_l, g_c_l);

    cudaFuncSetAttribute(gemm_qkv, cudaFuncAttributeMaxDynamicSharedMemorySize, 98304);
    cudaFuncSetAttribute(attn_bs, cudaFuncAttributeMaxDynamicSharedMemorySize, 65536);

    {
        int n4hs = MROWS * EMB / 4;
        int n4w = EMB * EMB / 4;
        split_f32<<<n4hs / 256, 256>>>((const float4*)hs, hs_h, hs_l, n4hs);          // 0
        split_w4<<<dim3(n4w / 256, 4), 256>>>((const float4*)wq, (const float4*)wk,
            (const float4*)wv, (const float4*)wo,
            wq_h, wq_l, wk_h, wk_l, wv_h, wv_l, wo_h, wo_l, n4w);                     // 1
    }
    init_mask_kernel<<<1, 32>>>();                                                    // 2

    dim3 gqkv(EMB / 128, MROWS / 128, 3); // (8, 32, 3)
    gemm_qkv<<<gqkv, 256, 98304>>>(hs_h, hs_l,
        wq_h, wq_l, bq, wk_h, wk_l, bk, wv_h, wv_l, bv,
        q_h, q_l, k_h, k_l, v_h, v_l, nullptr, 1);                                    // 3

    noop_kernel<<<1, 32>>>();                                                         // 4 (spacer)

    attn_bs<<<dim3(NB, BATCH * NH), 128, 65536>>>(q_h, q_l, k_h, k_l, v_h, v_l, c_h, c_l); // 5 <- ncu

    dim3 go(EMB / 128, MROWS / 128, 1);
    gemm_qkv<<<go, 256, 98304>>>(c_h, c_l,
        wo_h, wo_l, bo, wo_h, wo_l, bo, wo_h, wo_l, bo,
        nullptr, nullptr, nullptr, nullptr, nullptr, nullptr, out, 0);                // 6
}

// round 15
// speedup vs baseline: 1.4285x; 1.3986x over previous
#include <cuda_runtime.h>
#include <cuda_fp16.h>
#include <math.h>

typedef unsigned u32;
typedef unsigned long long u64;

#define BATCH 2
#define SEQN 2048
#define EMB 1024
#define NH 16
#define HD 64
#define NB 32
#define MROWS (BATCH*SEQN)   // 4096

// ---------------- scratch: static device globals ----------------
__device__ __half g_hs[MROWS*EMB];
__device__ __half g_wq_h[EMB*EMB], g_wq_l[EMB*EMB];
__device__ __half g_wk_h[EMB*EMB], g_wk_l[EMB*EMB];
__device__ __half g_wv_h[EMB*EMB], g_wv_l[EMB*EMB];
__device__ __half g_wo_h[EMB*EMB], g_wo_l[EMB*EMB];
__device__ __half g_q[MROWS*EMB];
__device__ __half g_k_h[MROWS*EMB], g_k_l[MROWS*EMB];
__device__ __half g_v_h[MROWS*EMB], g_v_l[MROWS*EMB];
__device__ __half g_c[MROWS*EMB];
__device__ unsigned g_blockmask[NB];

// ---------------- asm helpers ----------------
__device__ __forceinline__ u32 smem_u32(const void* p) {
    return (u32)__cvta_generic_to_shared(p);
}
__device__ __forceinline__ void ldsm4(u32 a[4], u32 addr) {
    asm volatile("ldmatrix.sync.aligned.m8n8.x4.shared.b16 {%0,%1,%2,%3}, [%4];"
        : "=r"(a[0]), "=r"(a[1]), "=r"(a[2]), "=r"(a[3]) : "r"(addr));
}
__device__ __forceinline__ void ldsm4t(u32 a[4], u32 addr) {
    asm volatile("ldmatrix.sync.aligned.m8n8.x4.trans.shared.b16 {%0,%1,%2,%3}, [%4];"
        : "=r"(a[0]), "=r"(a[1]), "=r"(a[2]), "=r"(a[3]) : "r"(addr));
}
__device__ __forceinline__ void mma16816(float d[4], const u32 a[4], u32 b0, u32 b1) {
    asm volatile("mma.sync.aligned.m16n8k16.row.col.f32.f16.f16.f32 "
        "{%0,%1,%2,%3},{%4,%5,%6,%7},{%8,%9},{%0,%1,%2,%3};"
        : "+f"(d[0]), "+f"(d[1]), "+f"(d[2]), "+f"(d[3])
        : "r"(a[0]), "r"(a[1]), "r"(a[2]), "r"(a[3]), "r"(b0), "r"(b1));
}
__device__ __forceinline__ void cpa16(u32 dst, const void* src) {
    asm volatile("cp.async.cg.shared.global [%0], [%1], 16;" :: "r"(dst), "l"(src));
}
#define CP_COMMIT asm volatile("cp.async.commit_group;" ::: "memory")
#define CP_WAIT0  asm volatile("cp.async.wait_group 0;" ::: "memory")
#define CP_WAIT1  asm volatile("cp.async.wait_group 1;" ::: "memory")

// swizzles: 64B-row tiles (GEMM) and 128B-row tiles (attention)
__device__ __forceinline__ u32 swzG(u32 off) { return off ^ (((off >> 7) & 3u) << 4); }
__device__ __forceinline__ u32 swzA(u32 off) { return off ^ ((off >> 3) & 0x70u); }

// pack two fp32 into one half2 word (round-to-nearest)
__device__ __forceinline__ u32 pack_h2(float a, float b) {
    __half2 h = __floats2half2_rn(a, b);
    return *reinterpret_cast<u32*>(&h);
}
// fp32 pair -> fp16 hi pair + fp16 lo pair
__device__ __forceinline__ void split_pair_h(float x0, float x1, u32& h, u32& l) {
    __half h0 = __float2half_rn(x0), h1 = __float2half_rn(x1);
    float r0 = x0 - __half2float(h0), r1 = x1 - __half2float(h1);
    __half l0 = __float2half_rn(r0), l1 = __float2half_rn(r1);
    __half2 hp; hp.x = h0; hp.y = h1;
    __half2 lp; lp.x = l0; lp.y = l1;
    h = *reinterpret_cast<u32*>(&hp);
    l = *reinterpret_cast<u32*>(&lp);
}

// ---------------- MT19937 mask init, warp-parallel twist ----------------
#define NGEN_BLOCKS 4
__global__ void init_mask_kernel() {
    __shared__ unsigned mt[624];
    __shared__ unsigned rnd[NGEN_BLOCKS * 624];
    const int t = threadIdx.x;

    if (t == 0) {
        unsigned s = 0u;
        for (int i = 0; i < 624; ++i) { mt[i] = s; s = 1812433253u * (s ^ (s >> 30)) + (unsigned)i + 1u; }
    }
    __syncwarp();

    auto twist_range = [&](int lo, int hi) {
        for (int base = lo; base < hi; base += 32) {
            int i = base + t;
            unsigned nv = 0; bool act = (i < hi);
            if (act) {
                unsigned y = (mt[i] & 0x80000000u) | (mt[(i + 1) % 624] & 0x7fffffffu);
                nv = mt[(i + 397) % 624] ^ (y >> 1) ^ ((y & 1u) ? 0x9908b0dfu : 0u);
            }
            __syncwarp();
            if (act) mt[i] = nv;
            __syncwarp();
        }
    };

    for (int blk = 0; blk < NGEN_BLOCKS; ++blk) {
        twist_range(0, 227);
        twist_range(227, 454);
        twist_range(454, 624);
        for (int i = t; i < 624; i += 32) {
            unsigned y = mt[i];
            y ^= y >> 11; y ^= (y << 7) & 0x9d2c5680u; y ^= (y << 15) & 0xefc60000u; y ^= y >> 18;
            rnd[blk * 624 + i] = y;
        }
        __syncwarp();
    }

    if (t != 0) return;

    int idx = 0;
    auto next32 = [&]() -> unsigned { return rnd[idx++]; };
    auto rand_interval = [&](unsigned maxv) -> unsigned {
        if (maxv == 0u) return 0u;
        unsigned mask = maxv;
        mask |= mask >> 1; mask |= mask >> 2; mask |= mask >> 4; mask |= mask >> 8; mask |= mask >> 16;
        unsigned v;
        do { v = next32() & mask; } while (v > maxv);
        return v;
    };
    unsigned bm[NB];
    bm[0] = 0xffffffffu;
    for (int qb = 1; qb < NB; ++qb) {
        unsigned m = 1u;
        int lo = qb - 3; if (lo < 0) lo = 0;
        int hi = qb + 3; if (hi > NB - 1) hi = NB - 1;
        for (int kb = lo; kb <= hi; ++kb) m |= (1u << kb);
        bm[qb] = m;
    }
    for (int b = 1; b < NB; ++b) {
        int avail[NB]; int pop = 0;
        for (int x = 1; x < NB; ++x)
            if ((x - b > 3) || (b - x > 3)) avail[pop++] = x;
        if (pop == 0) continue;
        int perm[NB];
        for (int i = 0; i < pop; ++i) perm[i] = i;
        for (int i = pop - 1; i > 0; --i) {
            unsigned j = rand_interval((unsigned)i);
            int tmp = perm[i]; perm[i] = perm[j]; perm[j] = tmp;
        }
        int take = pop < 3 ? pop : 3;
        for (int tsel = 0; tsel < take; ++tsel) bm[b] |= (1u << avail[perm[tsel]]);
    }
    for (int i = 0; i < NB; ++i) g_blockmask[i] = bm[i];
}

__global__ void noop_kernel() {}

// ---------------- fp32 -> fp16 conversions ----------------
// round only (for activations / A-side operands)
__global__ void round_f32(const float4* __restrict__ src, __half* __restrict__ h, int n4)
{
    int i = blockIdx.x * blockDim.x + threadIdx.x;
    if (i >= n4) return;
    float4 v = src[i];
    u32* hp = (u32*)h + 2 * i;
    hp[0] = pack_h2(v.x, v.y);
    hp[1] = pack_h2(v.z, v.w);
}

// hi/lo pair split for the 4 weight matrices
__global__ void split_w4(const float4* w0, const float4* w1, const float4* w2, const float4* w3,
                         __half* h0, __half* l0, __half* h1, __half* l1,
                         __half* h2, __half* l2, __half* h3, __half* l3,
                         int n4)
{
    int i = blockIdx.x * blockDim.x + threadIdx.x;
    if (i >= n4) return;
    int sel = blockIdx.y;
    const float4* src = (sel == 0) ? w0 : (sel == 1) ? w1 : (sel == 2) ? w2 : w3;
    __half* h = (sel == 0) ? h0 : (sel == 1) ? h1 : (sel == 2) ? h2 : h3;
    __half* l = (sel == 0) ? l0 : (sel == 1) ? l1 : (sel == 2) ? l2 : l3;
    float4 v = src[i];
    u32 a0, b0, a1, b1;
    split_pair_h(v.x, v.y, a0, b0);
    split_pair_h(v.z, v.w, a1, b1);
    u32* hp = (u32*)h + 2 * i;
    u32* lp = (u32*)l + 2 * i;
    hp[0] = a0; hp[1] = a1;
    lp[0] = b0; lp[1] = b1;
}

// ---------------- fp16 2-term GEMM: C = A @ W^T + bias ----------------
// A: single fp16 (rounded). W: fp16 hi/lo pair. D = A*Wh + A*Wl (fp32 acc).
// CTA 128x128, BK=32, 256 threads (8 warps 2x4), warp tile 64x32.
// 3-stage cp.async ring (stage = 24KB: A 8K, Wh 8K, Wl 8K), 1 sync/iter.
// Output modes: Cf!=null -> fp32; else z==0 -> single fp16 (Q/ctx); z==1/2 -> pair (K/V).
#define GSTG 24576
__global__ __launch_bounds__(256, 2) void gemm_qkv(
    const __half* __restrict__ A,
    const __half* __restrict__ W0h, const __half* __restrict__ W0l, const float* __restrict__ b0v,
    const __half* __restrict__ W1h, const __half* __restrict__ W1l, const float* __restrict__ b1v,
    const __half* __restrict__ W2h, const __half* __restrict__ W2l, const float* __restrict__ b2v,
    __half* __restrict__ Qout,
    __half* __restrict__ Kh, __half* __restrict__ Kl,
    __half* __restrict__ Vh, __half* __restrict__ Vl,
    float* __restrict__ Cf)
{
    extern __shared__ char smraw[];
    const u32 sbase = smem_u32(smraw);
    const int t = threadIdx.x;
    const int lane = t & 31, warp = t >> 5;
    const int wy = warp >> 2, wx = warp & 3;
    const int m0 = blockIdx.y * 128, n0 = blockIdx.x * 128;
    const int z = blockIdx.z;
    const int K = EMB, N = EMB;

    const __half* Wh = (z == 0) ? W0h : (z == 1) ? W1h : W2h;
    const __half* Wl = (z == 0) ? W0l : (z == 1) ? W1l : W2l;
    const float* bias = (z == 0) ? b0v : (z == 1) ? b1v : b2v;

    const int cch = t & 3;
    const int r0 = t >> 2;
    const u32 d0 = swzG((u32)(r0 * 64 + cch * 16));
    const u32 d1 = swzG((u32)((r0 + 64) * 64 + cch * 16));
    const char* pA0 = (const char*)(A + (size_t)(m0 + r0) * K) + cch * 16;
    const char* pA1 = (const char*)(A + (size_t)(m0 + r0 + 64) * K) + cch * 16;
    const char* pWh0 = (const char*)(Wh + (size_t)(n0 + r0) * K) + cch * 16;
    const char* pWh1 = (const char*)(Wh + (size_t)(n0 + r0 + 64) * K) + cch * 16;
    const char* pWl0 = (const char*)(Wl + (size_t)(n0 + r0) * K) + cch * 16;
    const char* pWl1 = (const char*)(Wl + (size_t)(n0 + r0 + 64) * K) + cch * 16;

    const int lr = lane & 15, lc = lane >> 4;
    u32 offA[4][2], offB[2][2];
#pragma unroll
    for (int i = 0; i < 4; ++i)
#pragma unroll
        for (int s = 0; s < 2; ++s)
            offA[i][s] = swzG((u32)((64 * wy + 16 * i + lr) * 64 + (2 * s + lc) * 16));
#pragma unroll
    for (int jg = 0; jg < 2; ++jg)
#pragma unroll
        for (int s = 0; s < 2; ++s)
            offB[jg][s] = swzG((u32)((32 * wx + 16 * jg + lr) * 64 + (2 * s + lc) * 16));

    float acc[4][4][4];
#pragma unroll
    for (int i = 0; i < 4; ++i)
#pragma unroll
        for (int j = 0; j < 4; ++j)
#pragma unroll
            for (int r = 0; r < 4; ++r) acc[i][j][r] = 0.f;

    auto prefetch = [&](int st, int kt) {
        u32 b = sbase + st * GSTG;
        size_t ko = (size_t)kt * 64;   // 32 fp16 = 64B
        cpa16(b + d0,          pA0 + ko);  cpa16(b + d1,          pA1 + ko);
        cpa16(b + 8192 + d0,   pWh0 + ko); cpa16(b + 8192 + d1,   pWh1 + ko);
        cpa16(b + 16384 + d0,  pWl0 + ko); cpa16(b + 16384 + d1,  pWl1 + ko);
    };

    prefetch(0, 0); CP_COMMIT;
    prefetch(1, 1); CP_COMMIT;

    const int KT = K / 32;
    int stage = 0;
    for (int kt = 0; kt < KT; ++kt) {
        if (kt + 1 < KT) { CP_WAIT1; } else { CP_WAIT0; }
        __syncthreads();
        if (kt + 2 < KT) {
            int ps = stage + 2; if (ps >= 3) ps -= 3;
            prefetch(ps, kt + 2); CP_COMMIT;
        }
        u32 base = sbase + stage * GSTG;
#pragma unroll
        for (int s = 0; s < 2; ++s) {
            u32 bh[2][4], bl_[2][4];
#pragma unroll
            for (int jg = 0; jg < 2; ++jg) {
                ldsm4(bh[jg], base + 8192 + offB[jg][s]);
                ldsm4(bl_[jg], base + 16384 + offB[jg][s]);
            }
            u32 af[4][4];
#pragma unroll
            for (int i = 0; i < 4; ++i) ldsm4(af[i], base + offA[i][s]);
#pragma unroll
            for (int i = 0; i < 4; ++i)
#pragma unroll
                for (int j = 0; j < 4; ++j) {
                    int jg = j >> 1, sel = j & 1;
                    mma16816(acc[i][j], af[i], bh[jg][sel], bh[jg][sel + 2]);
                    mma16816(acc[i][j], af[i], bl_[jg][sel], bl_[jg][sel + 2]);
                }
        }
        if (++stage == 3) stage = 0;
    }

    const int g = lane >> 2, tg = lane & 3;
    __half* Ph = (z == 1) ? Kh : Vh;
    __half* Pl = (z == 1) ? Kl : Vl;
#pragma unroll
    for (int i = 0; i < 4; ++i) {
        int rA = m0 + 64 * wy + 16 * i + g;
        int rB = rA + 8;
#pragma unroll
        for (int j = 0; j < 4; ++j) {
            int col = n0 + 32 * wx + 8 * j + 2 * tg;
            float b0 = bias[col], b1 = bias[col + 1];
            float v0 = acc[i][j][0] + b0, v1 = acc[i][j][1] + b1;
            float v2 = acc[i][j][2] + b0, v3 = acc[i][j][3] + b1;
            if (Cf) {
                *(float2*)(Cf + (size_t)rA * N + col) = make_float2(v0, v1);
                *(float2*)(Cf + (size_t)rB * N + col) = make_float2(v2, v3);
            } else if (z == 0) {
                *(u32*)(Qout + (size_t)rA * N + col) = pack_h2(v0, v1);
                *(u32*)(Qout + (size_t)rB * N + col) = pack_h2(v2, v3);
            } else {
                u32 hh, ll;
                split_pair_h(v0, v1, hh, ll);
                *(u32*)(Ph + (size_t)rA * N + col) = hh;
                *(u32*)(Pl + (size_t)rA * N + col) = ll;
                split_pair_h(v2, v3, hh, ll);
                *(u32*)(Ph + (size_t)rB * N + col) = hh;
                *(u32*)(Pl + (size_t)rB * N + col) = ll;
            }
        }
    }
}

// ---------------- block-sparse flash attention (fp16 2-term) ----------------
// 128 threads, 1 q-block/CTA. smem 64KB: KV buf0 [0,32K), buf1 [32K,64K).
// Q (single fp16, 8KB) overlaid into buf1 slot 0; fragments read before buf1 use.
__global__ __launch_bounds__(128, 3) void attn_bs(
    const __half* __restrict__ Q,
    const __half* __restrict__ Kh, const __half* __restrict__ Kl,
    const __half* __restrict__ Vh, const __half* __restrict__ Vl,
    __half* __restrict__ O)
{
    extern __shared__ char smraw[];
    const u32 sb = smem_u32(smraw);
    const int t = threadIdx.x;
    const int lane = t & 31, warp = t >> 5;
    const int qb = blockIdx.x;
    const int b = blockIdx.y >> 4, h = blockIdx.y & 15;
    const size_t gbase = (size_t)b * SEQN * EMB + (size_t)h * HD;
    const int lr = lane & 15, lc = lane >> 4;
    const int g = lane >> 2, tg = lane & 3;

    // Q load into buf1 slot 0: 512 chunks of 16B over 128 threads
#pragma unroll
    for (int it = 0; it < 4; ++it) {
        int id = t + 128 * it;
        int row = id >> 3, c = id & 7;
        u32 dst = sb + 32768 + swzA((u32)(row * 128 + c * 16));
        const char* src = (const char*)(Q + gbase + (size_t)(qb * 64 + row) * EMB) + c * 16;
        cpa16(dst, src);
    }

    const __half* kvsrc[4] = { Kh, Kl, Vh, Vl };
    auto loadKV = [&](int buf, int kb) {
#pragma unroll
        for (int it = 0; it < 16; ++it) {
            int id = t + 128 * it;
            int mat = it >> 2;
            int cid = id & 511;
            int row = cid >> 3, c = cid & 7;
            u32 dst = sb + buf * 32768 + mat * 8192 + swzA((u32)(row * 128 + c * 16));
            const char* src = (const char*)(kvsrc[mat] + gbase + (size_t)(kb * 64 + row) * EMB) + c * 16;
            cpa16(dst, src);
        }
    };

    unsigned rem = g_blockmask[qb];
    int kb = __ffs(rem) - 1; rem &= rem - 1;
    loadKV(0, kb);
    CP_COMMIT;
    CP_WAIT0;
    __syncthreads();

    // extract Q fragments (buf1 region then dead)
    u32 qh[4][4];
#pragma unroll
    for (int c = 0; c < 4; ++c) {
        u32 offQ = swzA((u32)((16 * warp + lr) * 128 + (2 * c + lc) * 16));
        ldsm4(qh[c], sb + 32768 + offQ);
    }
    __syncthreads();

    float o[8][4];
#pragma unroll
    for (int nt = 0; nt < 8; ++nt)
#pragma unroll
        for (int r = 0; r < 4; ++r) o[nt][r] = 0.f;
    float mrow0 = -INFINITY, mrow1 = -INFINITY, lrow0 = 0.f, lrow1 = 0.f;

    int buf = 0;
    bool first = true;

    while (kb >= 0) {
        int nxt = rem ? (__ffs(rem) - 1) : -1;
        if (nxt >= 0) { rem &= rem - 1; loadKV(buf ^ 1, nxt); CP_COMMIT; CP_WAIT1; }
        else { CP_WAIT0; }
        if (!first) __syncthreads();
        first = false;

        u32 kvb = sb + buf * 32768;

        float s[8][4];
#pragma unroll
        for (int nt = 0; nt < 8; ++nt)
#pragma unroll
            for (int r = 0; r < 4; ++r) s[nt][r] = 0.f;
#pragma unroll
        for (int c = 0; c < 4; ++c) {
#pragma unroll
            for (int jg = 0; jg < 4; ++jg) {
                u32 off = swzA((u32)((16 * jg + lr) * 128 + (2 * c + lc) * 16));
                u32 kh4[4], kl4[4];
                ldsm4(kh4, kvb + off);
                ldsm4(kl4, kvb + 8192 + off);
#pragma unroll
                for (int sel = 0; sel < 2; ++sel) {
                    int nt = 2 * jg + sel;
                    mma16816(s[nt], qh[c], kh4[sel], kh4[sel + 2]);
                    mma16816(s[nt], qh[c], kl4[sel], kl4[sel + 2]);
                }
            }
        }

        float mx0 = -INFINITY, mx1 = -INFINITY;
#pragma unroll
        for (int nt = 0; nt < 8; ++nt) {
            s[nt][0] *= 0.125f; s[nt][1] *= 0.125f; s[nt][2] *= 0.125f; s[nt][3] *= 0.125f;
            mx0 = fmaxf(mx0, fmaxf(s[nt][0], s[nt][1]));
            mx1 = fmaxf(mx1, fmaxf(s[nt][2], s[nt][3]));
        }
        mx0 = fmaxf(mx0, __shfl_xor_sync(0xffffffffu, mx0, 1, 4));
        mx0 = fmaxf(mx0, __shfl_xor_sync(0xffffffffu, mx0, 2, 4));
        mx1 = fmaxf(mx1, __shfl_xor_sync(0xffffffffu, mx1, 1, 4));
        mx1 = fmaxf(mx1, __shfl_xor_sync(0xffffffffu, mx1, 2, 4));
        float mn0 = fmaxf(mrow0, mx0), mn1 = fmaxf(mrow1, mx1);
        float a0 = __expf(mrow0 - mn0), a1 = __expf(mrow1 - mn1);
        float sum0 = 0.f, sum1 = 0.f;
#pragma unroll
        for (int nt = 0; nt < 8; ++nt) {
            s[nt][0] = __expf(s[nt][0] - mn0); s[nt][1] = __expf(s[nt][1] - mn0);
            s[nt][2] = __expf(s[nt][2] - mn1); s[nt][3] = __expf(s[nt][3] - mn1);
            sum0 += s[nt][0] + s[nt][1];
            sum1 += s[nt][2] + s[nt][3];
        }
        sum0 += __shfl_xor_sync(0xffffffffu, sum0, 1, 4);
        sum0 += __shfl_xor_sync(0xffffffffu, sum0, 2, 4);
        sum1 += __shfl_xor_sync(0xffffffffu, sum1, 1, 4);
        sum1 += __shfl_xor_sync(0xffffffffu, sum1, 2, 4);
        lrow0 = lrow0 * a0 + sum0; lrow1 = lrow1 * a1 + sum1;
        mrow0 = mn0; mrow1 = mn1;
#pragma unroll
        for (int nt = 0; nt < 8; ++nt) {
            o[nt][0] *= a0; o[nt][1] *= a0; o[nt][2] *= a1; o[nt][3] *= a1;
        }

        // P rounded to single fp16
        u32 ph[8][2];
#pragma unroll
        for (int nt = 0; nt < 8; ++nt) {
            ph[nt][0] = pack_h2(s[nt][0], s[nt][1]);
            ph[nt][1] = pack_h2(s[nt][2], s[nt][3]);
        }

#pragma unroll
        for (int c = 0; c < 4; ++c) {
            u32 aph[4] = { ph[2 * c][0], ph[2 * c][1], ph[2 * c + 1][0], ph[2 * c + 1][1] };
#pragma unroll
            for (int jg = 0; jg < 4; ++jg) {
                u32 off = swzA((u32)((16 * c + lr) * 128 + (2 * jg + lc) * 16));
                u32 vh4[4], vl4[4];
                ldsm4t(vh4, kvb + 16384 + off);
                ldsm4t(vl4, kvb + 24576 + off);
#pragma unroll
                for (int sel = 0; sel < 2; ++sel) {
                    int nt = 2 * jg + sel;
                    mma16816(o[nt], aph, vh4[2 * sel], vh4[2 * sel + 1]);
                    mma16816(o[nt], aph, vl4[2 * sel], vl4[2 * sel + 1]);
                }
            }
        }

        __syncthreads();
        buf ^= 1;
        kb = nxt;
    }

    float inv0 = 1.f / lrow0, inv1 = 1.f / lrow1;
    int row0 = qb * 64 + 16 * warp + g;
    int row1 = row0 + 8;
#pragma unroll
    for (int nt = 0; nt < 8; ++nt) {
        int col = 8 * nt + 2 * tg;
        size_t i0 = gbase + (size_t)row0 * EMB + col;
        size_t i1 = gbase + (size_t)row1 * EMB + col;
        *(u32*)(O + i0) = pack_h2(o[nt][0] * inv0, o[nt][1] * inv0);
        *(u32*)(O + i1) = pack_h2(o[nt][2] * inv1, o[nt][3] * inv1);
    }
}

// ---------------- launcher ----------------
extern "C" void kernel_launch(void* const* d_in, const int* in_sizes, int n_in,
                              void* d_out, int out_size)
{
    (void)in_sizes; (void)n_in; (void)out_size;
    const float* hs = (const float*)d_in[0];
    const float* wq = (const float*)d_in[1];
    const float* bq = (const float*)d_in[2];
    const float* wk = (const float*)d_in[3];
    const float* bk = (const float*)d_in[4];
    const float* wv = (const float*)d_in[5];
    const float* bv = (const float*)d_in[6];
    const float* wo = (const float*)d_in[7];
    const float* bo = (const float*)d_in[8];
    float* out = (float*)d_out;

    __half *hsb, *wq_h, *wq_l, *wk_h, *wk_l, *wv_h, *wv_l, *wo_h, *wo_l;
    __half *q, *k_h, *k_l, *v_h, *v_l, *c;
    cudaGetSymbolAddress((void**)&hsb, g_hs);
    cudaGetSymbolAddress((void**)&wq_h, g_wq_h); cudaGetSymbolAddress((void**)&wq_l, g_wq_l);
    cudaGetSymbolAddress((void**)&wk_h, g_wk_h); cudaGetSymbolAddress((void**)&wk_l, g_wk_l);
    cudaGetSymbolAddress((void**)&wv_h, g_wv_h); cudaGetSymbolAddress((void**)&wv_l, g_wv_l);
    cudaGetSymbolAddress((void**)&wo_h, g_wo_h); cudaGetSymbolAddress((void**)&wo_l, g_wo_l);
    cudaGetSymbolAddress((void**)&q, g_q);
    cudaGetSymbolAddress((void**)&k_h, g_k_h);   cudaGetSymbolAddress((void**)&k_l, g_k_l);
    cudaGetSymbolAddress((void**)&v_h, g_v_h);   cudaGetSymbolAddress((void**)&v_l, g_v_l);
    cudaGetSymbolAddress((void**)&c, g_c);

    cudaFuncSetAttribute(gemm_qkv, cudaFuncAttributeMaxDynamicSharedMemorySize, 3 * GSTG);
    cudaFuncSetAttribute(attn_bs, cudaFuncAttributeMaxDynamicSharedMemorySize, 65536);

    {
        int n4hs = MROWS * EMB / 4;
        int n4w = EMB * EMB / 4;
        round_f32<<<n4hs / 256, 256>>>((const float4*)hs, hsb, n4hs);                 // 0
        split_w4<<<dim3(n4w / 256, 4), 256>>>((const float4*)wq, (const float4*)wk,
            (const float4*)wv, (const float4*)wo,
            wq_h, wq_l, wk_h, wk_l, wv_h, wv_l, wo_h, wo_l, n4w);                     // 1
    }
    init_mask_kernel<<<1, 32>>>();                                                    // 2

    dim3 gqkv(EMB / 128, MROWS / 128, 3); // (8, 32, 3)
    gemm_qkv<<<gqkv, 256, 3 * GSTG>>>(hsb,
        wq_h, wq_l, bq, wk_h, wk_l, bk, wv_h, wv_l, bv,
        q, k_h, k_l, v_h, v_l, nullptr);                                              // 3

    noop_kernel<<<1, 32>>>();                                                         // 4 (spacer)

    attn_bs<<<dim3(NB, BATCH * NH), 128, 65536>>>(q, k_h, k_l, v_h, v_l, c);          // 5

    dim3 go(EMB / 128, MROWS / 128, 1);
    gemm_qkv<<<go, 256, 3 * GSTG>>>(c,
        wo_h, wo_l, bo, wo_h, wo_l, bo, wo_h, wo_l, bo,
        nullptr, nullptr, nullptr, nullptr, nullptr, out);                            // 6
}

// round 17
// speedup vs baseline: 1.4963x; 1.0475x over previous
#include <cuda_runtime.h>
#include <cuda_fp16.h>
#include <math.h>

typedef unsigned u32;
typedef unsigned long long u64;

#define BATCH 2
#define SEQN 2048
#define EMB 1024
#define NH 16
#define HD 64
#define NB 32
#define MROWS (BATCH*SEQN)   // 4096

// ---------------- scratch: static device globals ----------------
__device__ __half g_hs[MROWS*EMB];
__device__ __half g_wq_h[EMB*EMB], g_wq_l[EMB*EMB];
__device__ __half g_wk_h[EMB*EMB], g_wk_l[EMB*EMB];
__device__ __half g_wv_h[EMB*EMB], g_wv_l[EMB*EMB];
__device__ __half g_wo_h[EMB*EMB], g_wo_l[EMB*EMB];
__device__ __half g_q[MROWS*EMB];
__device__ __half g_k[MROWS*EMB];
__device__ __half g_v[MROWS*EMB];
__device__ __half g_c[MROWS*EMB];
__device__ unsigned g_blockmask[NB];

// ---------------- asm helpers ----------------
__device__ __forceinline__ u32 smem_u32(const void* p) {
    return (u32)__cvta_generic_to_shared(p);
}
__device__ __forceinline__ void ldsm4(u32 a[4], u32 addr) {
    asm volatile("ldmatrix.sync.aligned.m8n8.x4.shared.b16 {%0,%1,%2,%3}, [%4];"
        : "=r"(a[0]), "=r"(a[1]), "=r"(a[2]), "=r"(a[3]) : "r"(addr));
}
__device__ __forceinline__ void ldsm4t(u32 a[4], u32 addr) {
    asm volatile("ldmatrix.sync.aligned.m8n8.x4.trans.shared.b16 {%0,%1,%2,%3}, [%4];"
        : "=r"(a[0]), "=r"(a[1]), "=r"(a[2]), "=r"(a[3]) : "r"(addr));
}
__device__ __forceinline__ void mma16816(float d[4], const u32 a[4], u32 b0, u32 b1) {
    asm volatile("mma.sync.aligned.m16n8k16.row.col.f32.f16.f16.f32 "
        "{%0,%1,%2,%3},{%4,%5,%6,%7},{%8,%9},{%0,%1,%2,%3};"
        : "+f"(d[0]), "+f"(d[1]), "+f"(d[2]), "+f"(d[3])
        : "r"(a[0]), "r"(a[1]), "r"(a[2]), "r"(a[3]), "r"(b0), "r"(b1));
}
__device__ __forceinline__ void cpa16(u32 dst, const void* src) {
    asm volatile("cp.async.cg.shared.global [%0], [%1], 16;" :: "r"(dst), "l"(src));
}
#define CP_COMMIT asm volatile("cp.async.commit_group;" ::: "memory")
#define CP_WAIT0  asm volatile("cp.async.wait_group 0;" ::: "memory")
#define CP_WAIT1  asm volatile("cp.async.wait_group 1;" ::: "memory")

// swizzles: 64B-row tiles (GEMM) and 128B-row tiles (attention)
__device__ __forceinline__ u32 swzG(u32 off) { return off ^ (((off >> 7) & 3u) << 4); }
__device__ __forceinline__ u32 swzA(u32 off) { return off ^ ((off >> 3) & 0x70u); }

// pack two fp32 into one half2 word (round-to-nearest)
__device__ __forceinline__ u32 pack_h2(float a, float b) {
    __half2 h = __floats2half2_rn(a, b);
    return *reinterpret_cast<u32*>(&h);
}
// fp32 pair -> fp16 hi pair + fp16 lo pair
__device__ __forceinline__ void split_pair_h(float x0, float x1, u32& h, u32& l) {
    __half h0 = __float2half_rn(x0), h1 = __float2half_rn(x1);
    float r0 = x0 - __half2float(h0), r1 = x1 - __half2float(h1);
    __half l0 = __float2half_rn(r0), l1 = __float2half_rn(r1);
    __half2 hp; hp.x = h0; hp.y = h1;
    __half2 lp; lp.x = l0; lp.y = l1;
    h = *reinterpret_cast<u32*>(&hp);
    l = *reinterpret_cast<u32*>(&lp);
}

// ---------------- MT19937 mask init, warp-parallel twist ----------------
#define NGEN_BLOCKS 4
__global__ void init_mask_kernel() {
    __shared__ unsigned mt[624];
    __shared__ unsigned rnd[NGEN_BLOCKS * 624];
    const int t = threadIdx.x;

    if (t == 0) {
        unsigned s = 0u;
        for (int i = 0; i < 624; ++i) { mt[i] = s; s = 1812433253u * (s ^ (s >> 30)) + (unsigned)i + 1u; }
    }
    __syncwarp();

    auto twist_range = [&](int lo, int hi) {
        for (int base = lo; base < hi; base += 32) {
            int i = base + t;
            unsigned nv = 0; bool act = (i < hi);
            if (act) {
                unsigned y = (mt[i] & 0x80000000u) | (mt[(i + 1) % 624] & 0x7fffffffu);
                nv = mt[(i + 397) % 624] ^ (y >> 1) ^ ((y & 1u) ? 0x9908b0dfu : 0u);
            }
            __syncwarp();
            if (act) mt[i] = nv;
            __syncwarp();
        }
    };

    for (int blk = 0; blk < NGEN_BLOCKS; ++blk) {
        twist_range(0, 227);
        twist_range(227, 454);
        twist_range(454, 624);
        for (int i = t; i < 624; i += 32) {
            unsigned y = mt[i];
            y ^= y >> 11; y ^= (y << 7) & 0x9d2c5680u; y ^= (y << 15) & 0xefc60000u; y ^= y >> 18;
            rnd[blk * 624 + i] = y;
        }
        __syncwarp();
    }

    if (t != 0) return;

    int idx = 0;
    auto next32 = [&]() -> unsigned { return rnd[idx++]; };
    auto rand_interval = [&](unsigned maxv) -> unsigned {
        if (maxv == 0u) return 0u;
        unsigned mask = maxv;
        mask |= mask >> 1; mask |= mask >> 2; mask |= mask >> 4; mask |= mask >> 8; mask |= mask >> 16;
        unsigned v;
        do { v = next32() & mask; } while (v > maxv);
        return v;
    };
    unsigned bm[NB];
    bm[0] = 0xffffffffu;
    for (int qb = 1; qb < NB; ++qb) {
        unsigned m = 1u;
        int lo = qb - 3; if (lo < 0) lo = 0;
        int hi = qb + 3; if (hi > NB - 1) hi = NB - 1;
        for (int kb = lo; kb <= hi; ++kb) m |= (1u << kb);
        bm[qb] = m;
    }
    for (int b = 1; b < NB; ++b) {
        int avail[NB]; int pop = 0;
        for (int x = 1; x < NB; ++x)
            if ((x - b > 3) || (b - x > 3)) avail[pop++] = x;
        if (pop == 0) continue;
        int perm[NB];
        for (int i = 0; i < pop; ++i) perm[i] = i;
        for (int i = pop - 1; i > 0; --i) {
            unsigned j = rand_interval((unsigned)i);
            int tmp = perm[i]; perm[i] = perm[j]; perm[j] = tmp;
        }
        int take = pop < 3 ? pop : 3;
        for (int tsel = 0; tsel < take; ++tsel) bm[b] |= (1u << avail[perm[tsel]]);
    }
    for (int i = 0; i < NB; ++i) g_blockmask[i] = bm[i];
}

__global__ void noop_kernel() {}

// ---------------- fp32 -> fp16 conversions ----------------
__global__ void round_f32(const float4* __restrict__ src, __half* __restrict__ h, int n4)
{
    int i = blockIdx.x * blockDim.x + threadIdx.x;
    if (i >= n4) return;
    float4 v = src[i];
    u32* hp = (u32*)h + 2 * i;
    hp[0] = pack_h2(v.x, v.y);
    hp[1] = pack_h2(v.z, v.w);
}

__global__ void split_w4(const float4* w0, const float4* w1, const float4* w2, const float4* w3,
                         __half* h0, __half* l0, __half* h1, __half* l1,
                         __half* h2, __half* l2, __half* h3, __half* l3,
                         int n4)
{
    int i = blockIdx.x * blockDim.x + threadIdx.x;
    if (i >= n4) return;
    int sel = blockIdx.y;
    const float4* src = (sel == 0) ? w0 : (sel == 1) ? w1 : (sel == 2) ? w2 : w3;
    __half* h = (sel == 0) ? h0 : (sel == 1) ? h1 : (sel == 2) ? h2 : h3;
    __half* l = (sel == 0) ? l0 : (sel == 1) ? l1 : (sel == 2) ? l2 : l3;
    float4 v = src[i];
    u32 a0, b0, a1, b1;
    split_pair_h(v.x, v.y, a0, b0);
    split_pair_h(v.z, v.w, a1, b1);
    u32* hp = (u32*)h + 2 * i;
    u32* lp = (u32*)l + 2 * i;
    hp[0] = a0; hp[1] = a1;
    lp[0] = b0; lp[1] = b1;
}

// ---------------- fp16 2-term GEMM: C = A @ W^T + bias ----------------
// A: single fp16. W: fp16 hi/lo pair. D = A*Wh + A*Wl (fp32 acc).
// CTA 128x128, BK=32, 256 threads, warp tile 64x32, 3-stage ring, 1 sync/iter.
// Output: Cf!=null -> fp32; else single rounded fp16 into Cout (Q/K/V/ctx).
#define GSTG 24576
__global__ __launch_bounds__(256, 2) void gemm_qkv(
    const __half* __restrict__ A,
    const __half* __restrict__ W0h, const __half* __restrict__ W0l, const float* __restrict__ b0v,
    const __half* __restrict__ W1h, const __half* __restrict__ W1l, const float* __restrict__ b1v,
    const __half* __restrict__ W2h, const __half* __restrict__ W2l, const float* __restrict__ b2v,
    __half* __restrict__ C0, __half* __restrict__ C1, __half* __restrict__ C2,
    float* __restrict__ Cf)
{
    extern __shared__ char smraw[];
    const u32 sbase = smem_u32(smraw);
    const int t = threadIdx.x;
    const int lane = t & 31, warp = t >> 5;
    const int wy = warp >> 2, wx = warp & 3;
    const int m0 = blockIdx.y * 128, n0 = blockIdx.x * 128;
    const int z = blockIdx.z;
    const int K = EMB, N = EMB;

    const __half* Wh = (z == 0) ? W0h : (z == 1) ? W1h : W2h;
    const __half* Wl = (z == 0) ? W0l : (z == 1) ? W1l : W2l;
    const float* bias = (z == 0) ? b0v : (z == 1) ? b1v : b2v;
    __half* Cout      = (z == 0) ? C0 : (z == 1) ? C1 : C2;

    const int cch = t & 3;
    const int r0 = t >> 2;
    const u32 d0 = swzG((u32)(r0 * 64 + cch * 16));
    const u32 d1 = swzG((u32)((r0 + 64) * 64 + cch * 16));
    const char* pA0 = (const char*)(A + (size_t)(m0 + r0) * K) + cch * 16;
    const char* pA1 = (const char*)(A + (size_t)(m0 + r0 + 64) * K) + cch * 16;
    const char* pWh0 = (const char*)(Wh + (size_t)(n0 + r0) * K) + cch * 16;
    const char* pWh1 = (const char*)(Wh + (size_t)(n0 + r0 + 64) * K) + cch * 16;
    const char* pWl0 = (const char*)(Wl + (size_t)(n0 + r0) * K) + cch * 16;
    const char* pWl1 = (const char*)(Wl + (size_t)(n0 + r0 + 64) * K) + cch * 16;

    const int lr = lane & 15, lc = lane >> 4;
    u32 offA[4][2], offB[2][2];
#pragma unroll
    for (int i = 0; i < 4; ++i)
#pragma unroll
        for (int s = 0; s < 2; ++s)
            offA[i][s] = swzG((u32)((64 * wy + 16 * i + lr) * 64 + (2 * s + lc) * 16));
#pragma unroll
    for (int jg = 0; jg < 2; ++jg)
#pragma unroll
        for (int s = 0; s < 2; ++s)
            offB[jg][s] = swzG((u32)((32 * wx + 16 * jg + lr) * 64 + (2 * s + lc) * 16));

    float acc[4][4][4];
#pragma unroll
    for (int i = 0; i < 4; ++i)
#pragma unroll
        for (int j = 0; j < 4; ++j)
#pragma unroll
            for (int r = 0; r < 4; ++r) acc[i][j][r] = 0.f;

    auto prefetch = [&](int st, int kt) {
        u32 b = sbase + st * GSTG;
        size_t ko = (size_t)kt * 64;
        cpa16(b + d0,          pA0 + ko);  cpa16(b + d1,          pA1 + ko);
        cpa16(b + 8192 + d0,   pWh0 + ko); cpa16(b + 8192 + d1,   pWh1 + ko);
        cpa16(b + 16384 + d0,  pWl0 + ko); cpa16(b + 16384 + d1,  pWl1 + ko);
    };

    prefetch(0, 0); CP_COMMIT;
    prefetch(1, 1); CP_COMMIT;

    const int KT = K / 32;
    int stage = 0;
    for (int kt = 0; kt < KT; ++kt) {
        if (kt + 1 < KT) { CP_WAIT1; } else { CP_WAIT0; }
        __syncthreads();
        if (kt + 2 < KT) {
            int ps = stage + 2; if (ps >= 3) ps -= 3;
            prefetch(ps, kt + 2); CP_COMMIT;
        }
        u32 base = sbase + stage * GSTG;
#pragma unroll
        for (int s = 0; s < 2; ++s) {
            u32 bh[2][4], bl_[2][4];
#pragma unroll
            for (int jg = 0; jg < 2; ++jg) {
                ldsm4(bh[jg], base + 8192 + offB[jg][s]);
                ldsm4(bl_[jg], base + 16384 + offB[jg][s]);
            }
            u32 af[4][4];
#pragma unroll
            for (int i = 0; i < 4; ++i) ldsm4(af[i], base + offA[i][s]);
#pragma unroll
            for (int i = 0; i < 4; ++i)
#pragma unroll
                for (int j = 0; j < 4; ++j) {
                    int jg = j >> 1, sel = j & 1;
                    mma16816(acc[i][j], af[i], bh[jg][sel], bh[jg][sel + 2]);
                    mma16816(acc[i][j], af[i], bl_[jg][sel], bl_[jg][sel + 2]);
                }
        }
        if (++stage == 3) stage = 0;
    }

    const int g = lane >> 2, tg = lane & 3;
#pragma unroll
    for (int i = 0; i < 4; ++i) {
        int rA = m0 + 64 * wy + 16 * i + g;
        int rB = rA + 8;
#pragma unroll
        for (int j = 0; j < 4; ++j) {
            int col = n0 + 32 * wx + 8 * j + 2 * tg;
            float b0 = bias[col], b1 = bias[col + 1];
            float v0 = acc[i][j][0] + b0, v1 = acc[i][j][1] + b1;
            float v2 = acc[i][j][2] + b0, v3 = acc[i][j][3] + b1;
            if (Cf) {
                *(float2*)(Cf + (size_t)rA * N + col) = make_float2(v0, v1);
                *(float2*)(Cf + (size_t)rB * N + col) = make_float2(v2, v3);
            } else {
                *(u32*)(Cout + (size_t)rA * N + col) = pack_h2(v0, v1);
                *(u32*)(Cout + (size_t)rB * N + col) = pack_h2(v2, v3);
            }
        }
    }
}

// ---------------- block-sparse flash attention (all-fp16 single) ----------------
// 128 threads, 1 q-block/CTA. smem 32KB: KV buf0 [0,16K), buf1 [16K,32K).
// Per buffer: K 8KB + V 8KB. Q (8KB) overlaid into buf1's K slot; fragments
// read before buf1 is first written. 4 CTAs/SM.
__global__ __launch_bounds__(128, 4) void attn_bs(
    const __half* __restrict__ Q,
    const __half* __restrict__ K,
    const __half* __restrict__ V,
    __half* __restrict__ O)
{
    extern __shared__ char smraw[];
    const u32 sb = smem_u32(smraw);
    const int t = threadIdx.x;
    const int lane = t & 31, warp = t >> 5;
    const int qb = blockIdx.x;
    const int b = blockIdx.y >> 4, h = blockIdx.y & 15;
    const size_t gbase = (size_t)b * SEQN * EMB + (size_t)h * HD;
    const int lr = lane & 15, lc = lane >> 4;
    const int g = lane >> 2, tg = lane & 3;

    // Q load into buf1 K-slot: 512 chunks of 16B over 128 threads
#pragma unroll
    for (int it = 0; it < 4; ++it) {
        int id = t + 128 * it;
        int row = id >> 3, c = id & 7;
        u32 dst = sb + 16384 + swzA((u32)(row * 128 + c * 16));
        const char* src = (const char*)(Q + gbase + (size_t)(qb * 64 + row) * EMB) + c * 16;
        cpa16(dst, src);
    }

    auto loadKV = [&](int buf, int kb) {
#pragma unroll
        for (int it = 0; it < 8; ++it) {
            int id = t + 128 * it;
            int mat = id >> 9;          // 0=K 1=V
            int cid = id & 511;
            int row = cid >> 3, c = cid & 7;
            u32 dst = sb + buf * 16384 + mat * 8192 + swzA((u32)(row * 128 + c * 16));
            const __half* srcb = mat ? V : K;
            const char* src = (const char*)(srcb + gbase + (size_t)(kb * 64 + row) * EMB) + c * 16;
            cpa16(dst, src);
        }
    };

    unsigned rem = g_blockmask[qb];
    int kb = __ffs(rem) - 1; rem &= rem - 1;
    loadKV(0, kb);
    CP_COMMIT;
    CP_WAIT0;
    __syncthreads();

    // extract Q fragments (buf1 region then dead)
    u32 qh[4][4];
#pragma unroll
    for (int c = 0; c < 4; ++c) {
        u32 offQ = swzA((u32)((16 * warp + lr) * 128 + (2 * c + lc) * 16));
        ldsm4(qh[c], sb + 16384 + offQ);
    }
    __syncthreads();

    float o[8][4];
#pragma unroll
    for (int nt = 0; nt < 8; ++nt)
#pragma unroll
        for (int r = 0; r < 4; ++r) o[nt][r] = 0.f;
    float mrow0 = -INFINITY, mrow1 = -INFINITY, lrow0 = 0.f, lrow1 = 0.f;

    int buf = 0;
    bool first = true;

    while (kb >= 0) {
        int nxt = rem ? (__ffs(rem) - 1) : -1;
        if (nxt >= 0) { rem &= rem - 1; loadKV(buf ^ 1, nxt); CP_COMMIT; CP_WAIT1; }
        else { CP_WAIT0; }
        if (!first) __syncthreads();
        first = false;

        u32 kvb = sb + buf * 16384;

        float s[8][4];
#pragma unroll
        for (int nt = 0; nt < 8; ++nt)
#pragma unroll
            for (int r = 0; r < 4; ++r) s[nt][r] = 0.f;
#pragma unroll
        for (int c = 0; c < 4; ++c) {
#pragma unroll
            for (int jg = 0; jg < 4; ++jg) {
                u32 off = swzA((u32)((16 * jg + lr) * 128 + (2 * c + lc) * 16));
                u32 kh4[4];
                ldsm4(kh4, kvb + off);
#pragma unroll
                for (int sel = 0; sel < 2; ++sel) {
                    int nt = 2 * jg + sel;
                    mma16816(s[nt], qh[c], kh4[sel], kh4[sel + 2]);
                }
            }
        }

        float mx0 = -INFINITY, mx1 = -INFINITY;
#pragma unroll
        for (int nt = 0; nt < 8; ++nt) {
            s[nt][0] *= 0.125f; s[nt][1] *= 0.125f; s[nt][2] *= 0.125f; s[nt][3] *= 0.125f;
            mx0 = fmaxf(mx0, fmaxf(s[nt][0], s[nt][1]));
            mx1 = fmaxf(mx1, fmaxf(s[nt][2], s[nt][3]));
        }
        mx0 = fmaxf(mx0, __shfl_xor_sync(0xffffffffu, mx0, 1, 4));
        mx0 = fmaxf(mx0, __shfl_xor_sync(0xffffffffu, mx0, 2, 4));
        mx1 = fmaxf(mx1, __shfl_xor_sync(0xffffffffu, mx1, 1, 4));
        mx1 = fmaxf(mx1, __shfl_xor_sync(0xffffffffu, mx1, 2, 4));
        float mn0 = fmaxf(mrow0, mx0), mn1 = fmaxf(mrow1, mx1);
        float a0 = __expf(mrow0 - mn0), a1 = __expf(mrow1 - mn1);
        float sum0 = 0.f, sum1 = 0.f;
#pragma unroll
        for (int nt = 0; nt < 8; ++nt) {
            s[nt][0] = __expf(s[nt][0] - mn0); s[nt][1] = __expf(s[nt][1] - mn0);
            s[nt][2] = __expf(s[nt][2] - mn1); s[nt][3] = __expf(s[nt][3] - mn1);
            sum0 += s[nt][0] + s[nt][1];
            sum1 += s[nt][2] + s[nt][3];
        }
        sum0 += __shfl_xor_sync(0xffffffffu, sum0, 1, 4);
        sum0 += __shfl_xor_sync(0xffffffffu, sum0, 2, 4);
        sum1 += __shfl_xor_sync(0xffffffffu, sum1, 1, 4);
        sum1 += __shfl_xor_sync(0xffffffffu, sum1, 2, 4);
        lrow0 = lrow0 * a0 + sum0; lrow1 = lrow1 * a1 + sum1;
        mrow0 = mn0; mrow1 = mn1;
#pragma unroll
        for (int nt = 0; nt < 8; ++nt) {
            o[nt][0] *= a0; o[nt][1] *= a0; o[nt][2] *= a1; o[nt][3] *= a1;
        }

        u32 ph[8][2];
#pragma unroll
        for (int nt = 0; nt < 8; ++nt) {
            ph[nt][0] = pack_h2(s[nt][0], s[nt][1]);
            ph[nt][1] = pack_h2(s[nt][2], s[nt][3]);
        }

#pragma unroll
        for (int c = 0; c < 4; ++c) {
            u32 aph[4] = { ph[2 * c][0], ph[2 * c][1], ph[2 * c + 1][0], ph[2 * c + 1][1] };
#pragma unroll
            for (int jg = 0; jg < 4; ++jg) {
                u32 off = swzA((u32)((16 * c + lr) * 128 + (2 * jg + lc) * 16));
                u32 vh4[4];
                ldsm4t(vh4, kvb + 8192 + off);
#pragma unroll
                for (int sel = 0; sel < 2; ++sel) {
                    int nt = 2 * jg + sel;
                    mma16816(o[nt], aph, vh4[2 * sel], vh4[2 * sel + 1]);
                }
            }
        }

        __syncthreads();
        buf ^= 1;
        kb = nxt;
    }

    float inv0 = 1.f / lrow0, inv1 = 1.f / lrow1;
    int row0 = qb * 64 + 16 * warp + g;
    int row1 = row0 + 8;
#pragma unroll
    for (int nt = 0; nt < 8; ++nt) {
        int col = 8 * nt + 2 * tg;
        size_t i0 = gbase + (size_t)row0 * EMB + col;
        size_t i1 = gbase + (size_t)row1 * EMB + col;
        *(u32*)(O + i0) = pack_h2(o[nt][0] * inv0, o[nt][1] * inv0);
        *(u32*)(O + i1) = pack_h2(o[nt][2] * inv1, o[nt][3] * inv1);
    }
}

// ---------------- launcher ----------------
extern "C" void kernel_launch(void* const* d_in, const int* in_sizes, int n_in,
                              void* d_out, int out_size)
{
    (void)in_sizes; (void)n_in; (void)out_size;
    const float* hs = (const float*)d_in[0];
    const float* wq = (const float*)d_in[1];
    const float* bq = (const float*)d_in[2];
    const float* wk = (const float*)d_in[3];
    const float* bk = (const float*)d_in[4];
    const float* wv = (const float*)d_in[5];
    const float* bv = (const float*)d_in[6];
    const float* wo = (const float*)d_in[7];
    const float* bo = (const float*)d_in[8];
    float* out = (float*)d_out;

    __half *hsb, *wq_h, *wq_l, *wk_h, *wk_l, *wv_h, *wv_l, *wo_h, *wo_l;
    __half *q, *k, *v, *c;
    cudaGetSymbolAddress((void**)&hsb, g_hs);
    cudaGetSymbolAddress((void**)&wq_h, g_wq_h); cudaGetSymbolAddress((void**)&wq_l, g_wq_l);
    cudaGetSymbolAddress((void**)&wk_h, g_wk_h); cudaGetSymbolAddress((void**)&wk_l, g_wk_l);
    cudaGetSymbolAddress((void**)&wv_h, g_wv_h); cudaGetSymbolAddress((void**)&wv_l, g_wv_l);
    cudaGetSymbolAddress((void**)&wo_h, g_wo_h); cudaGetSymbolAddress((void**)&wo_l, g_wo_l);
    cudaGetSymbolAddress((void**)&q, g_q);
    cudaGetSymbolAddress((void**)&k, g_k);
    cudaGetSymbolAddress((void**)&v, g_v);
    cudaGetSymbolAddress((void**)&c, g_c);

    cudaFuncSetAttribute(gemm_qkv, cudaFuncAttributeMaxDynamicSharedMemorySize, 3 * GSTG);
    cudaFuncSetAttribute(attn_bs, cudaFuncAttributeMaxDynamicSharedMemorySize, 32768);

    {
        int n4hs = MROWS * EMB / 4;
        int n4w = EMB * EMB / 4;
        round_f32<<<n4hs / 256, 256>>>((const float4*)hs, hsb, n4hs);                 // 0
        split_w4<<<dim3(n4w / 256, 4), 256>>>((const float4*)wq, (const float4*)wk,
            (const float4*)wv, (const float4*)wo,
            wq_h, wq_l, wk_h, wk_l, wv_h, wv_l, wo_h, wo_l, n4w);                     // 1
    }
    init_mask_kernel<<<1, 32>>>();                                                    // 2

    dim3 gqkv(EMB / 128, MROWS / 128, 3); // (8, 32, 3)
    gemm_qkv<<<gqkv, 256, 3 * GSTG>>>(hsb,
        wq_h, wq_l, bq, wk_h, wk_l, bk, wv_h, wv_l, bv,
        q, k, v, nullptr);                                                            // 3

    noop_kernel<<<1, 32>>>();                                                         // 4 (spacer)

    attn_bs<<<dim3(NB, BATCH * NH), 128, 32768>>>(q, k, v, c);                        // 5 <- ncu

    dim3 go(EMB / 128, MROWS / 128, 1);
    gemm_qkv<<<go, 256, 3 * GSTG>>>(c,
        wo_h, wo_l, bo, wo_h, wo_l, bo, wo_h, wo_l, bo,
        nullptr, nullptr, nullptr, out);                                              // 6
}